// round 13
// baseline (speedup 1.0000x reference)
#include <cuda_runtime.h>
#include <cuda_bf16.h>
#include <math.h>
#include <cstdint>

#define NE 50000
#define NR 64
#define NT 400000

typedef unsigned long long u64;

// Scratch (static __device__ — no runtime allocation)
__device__ float    g_T[NE * 256];    // [ent][0:128]=emb@Wa2 (head/att), [128:256]=emb@Wg1+bg (head/msg)
__device__ float    g_P1[NE * 128];   // emb@Wa1 + ba (tail/att)
__device__ float    g_RG[NR * 256];   // [rel][0:128]=emb_rel@Wa3, [128:256]=emb_rel@Wg2
__device__ int      g_rowptr[NE + 1];
__device__ int      g_cursor[NE];
__device__ unsigned g_elist[NT];      // head | (rel<<16)
__device__ int      g_bsum[128];
__device__ int      g_boff[128];
// Pre-transposed bf16 weight images: [group][n][k], group 0=Wa1, 1=Wa2, 2=Wg1
__device__ __align__(16) unsigned short g_Bhi[3 * 16384];
__device__ __align__(16) unsigned short g_Blo[3 * 16384];

// ==================== warp-MMA helpers (sm_80+ PTX, works on sm_103) ====================
__device__ __forceinline__ uint32_t smem_u32(const void* p) {
    uint32_t a;
    asm("{ .reg .u64 t; cvta.to.shared.u64 t, %1; cvt.u32.u64 %0, t; }" : "=r"(a) : "l"(p));
    return a;
}
__device__ __forceinline__ void ldx4(uint32_t r[4], uint32_t addr) {
    asm volatile("ldmatrix.sync.aligned.m8n8.x4.shared.b16 {%0,%1,%2,%3}, [%4];"
                 : "=r"(r[0]), "=r"(r[1]), "=r"(r[2]), "=r"(r[3]) : "r"(addr));
}
__device__ __forceinline__ void ldx2(uint32_t r[2], uint32_t addr) {
    asm volatile("ldmatrix.sync.aligned.m8n8.x2.shared.b16 {%0,%1}, [%2];"
                 : "=r"(r[0]), "=r"(r[1]) : "r"(addr));
}
__device__ __forceinline__ void mma_bf16(float d[4], const uint32_t a[4], const uint32_t b[2]) {
    asm volatile("mma.sync.aligned.m16n8k16.row.col.f32.bf16.bf16.f32 "
                 "{%0,%1,%2,%3}, {%4,%5,%6,%7}, {%8,%9}, {%0,%1,%2,%3};"
                 : "+f"(d[0]), "+f"(d[1]), "+f"(d[2]), "+f"(d[3])
                 : "r"(a[0]), "r"(a[1]), "r"(a[2]), "r"(a[3]), "r"(b[0]), "r"(b[1]));
}
__device__ __forceinline__ float tanh_fast(float x) {
    float y; asm("tanh.approx.f32 %0, %1;" : "=f"(y) : "f"(x)); return y;
}

// ---------------- CSR build ----------------
__global__ void k_zero() {
    int i = blockIdx.x * blockDim.x + threadIdx.x;
    if (i <= NE) g_rowptr[i] = 0;
}

__global__ void k_count(const int* __restrict__ trip) {
    int e = blockIdx.x * blockDim.x + threadIdx.x;
    if (e < NT) atomicAdd(&g_rowptr[trip[3 * e + 2]], 1);
}

// 3-stage parallel scan
#define SCB 512
#define NSCB ((NE + SCB - 1) / SCB)   // 98

__global__ void k_scanA() {
    __shared__ int wsum[16];
    int b = blockIdx.x, t = threadIdx.x, lane = t & 31, w = t >> 5;
    int idx = b * SCB + t;
    int v = (idx < NE) ? g_rowptr[idx] : 0;
    #pragma unroll
    for (int o = 16; o > 0; o >>= 1) v += __shfl_down_sync(0xffffffffu, v, o);
    if (lane == 0) wsum[w] = v;
    __syncthreads();
    if (t == 0) {
        int s = 0;
        #pragma unroll
        for (int i = 0; i < 16; i++) s += wsum[i];
        g_bsum[b] = s;
    }
}

__global__ void k_scanB() {
    __shared__ int woff[4];
    int t = threadIdx.x, lane = t & 31, w = t >> 5;
    int v = (t < NSCB) ? g_bsum[t] : 0;
    int incl = v;
    #pragma unroll
    for (int o = 1; o < 32; o <<= 1) {
        int u = __shfl_up_sync(0xffffffffu, incl, o);
        if (lane >= o) incl += u;
    }
    if (lane == 31) woff[w] = incl;
    __syncthreads();
    int base = 0;
    for (int i = 0; i < w; i++) base += woff[i];
    if (t < NSCB) g_boff[t] = base + incl - v;
    if (t == 0) g_rowptr[NE] = NT;
}

__global__ void k_scanC() {
    __shared__ int wsum[16];
    int b = blockIdx.x, t = threadIdx.x, lane = t & 31, w = t >> 5;
    int idx = b * SCB + t;
    int v = (idx < NE) ? g_rowptr[idx] : 0;
    int incl = v;
    #pragma unroll
    for (int o = 1; o < 32; o <<= 1) {
        int u = __shfl_up_sync(0xffffffffu, incl, o);
        if (lane >= o) incl += u;
    }
    if (lane == 31) wsum[w] = incl;
    __syncthreads();
    if (w == 0 && lane < 16) {
        int x = wsum[lane];
        #pragma unroll
        for (int o = 1; o < 16; o <<= 1) {
            int u = __shfl_up_sync(0xffffu, x, o);
            if (lane >= o) x += u;
        }
        wsum[lane] = x;
    }
    __syncthreads();
    int excl = g_boff[b] + (w > 0 ? wsum[w - 1] : 0) + (incl - v);
    if (idx < NE) { g_rowptr[idx] = excl; g_cursor[idx] = excl; }
}

__global__ void k_scatter(const int* __restrict__ trip) {
    int e = blockIdx.x * blockDim.x + threadIdx.x;
    if (e < NT) {
        int h = trip[3 * e], r = trip[3 * e + 1], t = trip[3 * e + 2];
        int pos = atomicAdd(&g_cursor[t], 1);
        g_elist[pos] = (unsigned)h | ((unsigned)r << 16);
    }
}

// ---------------- weight prep: fp32 -> hi/lo bf16, transposed to [n][k] ----------------
__global__ void k_prepB(const float* __restrict__ Wa, const float* __restrict__ Wg) {
    int idx = blockIdx.x * blockDim.x + threadIdx.x;
    if (idx >= 3 * 16384) return;
    int g = idx >> 14, rem = idx & 16383;
    int n = rem >> 7, k = rem & 127;
    float w = (g == 0) ? Wa[k * 128 + n] : (g == 1) ? Wa[(128 + k) * 128 + n] : Wg[k * 128 + n];
    __nv_bfloat16 hi = __float2bfloat16(w);
    __nv_bfloat16 lo = __float2bfloat16(w - __bfloat162float(hi));
    unsigned short hb, lb;
    memcpy(&hb, &hi, 2); memcpy(&lb, &lo, 2);
    g_Bhi[idx] = hb;
    g_Blo[idx] = lb;
}

// ---------------- relation GEMM, MLP-optimized (FIXED indexing) ----------------
// 64 blocks (one relation each), 128 threads: half = tid>>6 selects Wa-att / Wg-msg,
// each thread owns exactly 2 output columns j0, j0+1 (64 threads x 2 = 128 cols).
// float2 W loads + unroll 16 -> 16 outstanding 8B loads per thread.
__global__ __launch_bounds__(128) void k_relgemm(const float* __restrict__ emb_rel,
                                                 const float* __restrict__ Wa,
                                                 const float* __restrict__ Wg) {
    __shared__ float er[128];
    int r = blockIdx.x;
    int tid = threadIdx.x;  // 128 threads
    er[tid] = emb_rel[r * 128 + tid];
    __syncthreads();
    int half = tid >> 6;          // 0: Wa-att, 1: Wg-msg
    int j0 = (tid & 63) * 2;      // 2 columns per thread
    const float* W = half ? (Wg + 128 * 128) : (Wa + 256 * 128);
    float ax = 0.f, ay = 0.f;
    #pragma unroll 16
    for (int k = 0; k < 128; k++) {
        float e = er[k];
        float2 w = __ldg((const float2*)(W + k * 128 + j0));
        ax += e * w.x;
        ay += e * w.y;
    }
    float2 o = make_float2(ax, ay);
    *(float2*)(g_RG + r * 256 + half * 128 + j0) = o;
}

// ---------------- HMMA entity GEMM: block M64 x (3 x N128) x K128, bf16 hi/lo 3-pass ----------------
#define SROW 272
#define SM_A_HI 0
#define SM_A_LO 17408
#define SM_B_HI 34816
#define SM_B_LO 69632
#define SM_TOTAL 104448

__global__ __launch_bounds__(256, 2) void k_mmagemm(const float* __restrict__ A,
                                                    const float* __restrict__ ba,
                                                    const float* __restrict__ bg) {
    extern __shared__ char smem[];
    uint32_t sb = smem_u32(smem);
    int tid = threadIdx.x, wid = tid >> 5, lane = tid & 31;
    int rowBase = blockIdx.x * 64;
    int warpM = wid & 1, warpN = wid >> 1;

    for (int i = tid; i < 2048; i += 256) {
        int m = i >> 5, k4 = (i & 31) * 4;
        int gr = rowBase + m;
        float4 v = make_float4(0.f, 0.f, 0.f, 0.f);
        if (gr < NE) v = *(const float4*)(A + (long)gr * 128 + k4);
        __nv_bfloat16 h0 = __float2bfloat16(v.x), h1 = __float2bfloat16(v.y);
        __nv_bfloat16 h2 = __float2bfloat16(v.z), h3 = __float2bfloat16(v.w);
        __nv_bfloat16 l0 = __float2bfloat16(v.x - __bfloat162float(h0));
        __nv_bfloat16 l1 = __float2bfloat16(v.y - __bfloat162float(h1));
        __nv_bfloat16 l2 = __float2bfloat16(v.z - __bfloat162float(h2));
        __nv_bfloat16 l3 = __float2bfloat16(v.w - __bfloat162float(h3));
        int off = m * SROW + k4 * 2;
        __nv_bfloat162 hv0; hv0.x = h0; hv0.y = h1;
        __nv_bfloat162 hv1; hv1.x = h2; hv1.y = h3;
        __nv_bfloat162 lv0; lv0.x = l0; lv0.y = l1;
        __nv_bfloat162 lv1; lv1.x = l2; lv1.y = l3;
        *(__nv_bfloat162*)(smem + SM_A_HI + off) = hv0;
        *(__nv_bfloat162*)(smem + SM_A_HI + off + 4) = hv1;
        *(__nv_bfloat162*)(smem + SM_A_LO + off) = lv0;
        *(__nv_bfloat162*)(smem + SM_A_LO + off + 4) = lv1;
    }

    uint32_t aAddr = sb + SM_A_HI + (uint32_t)((warpM * 32 + (lane & 15)) * SROW + ((lane >> 4) * 8) * 2);
    uint32_t bAddr = sb + SM_B_HI + (uint32_t)((warpN * 32 + (lane & 7)) * SROW + (((lane >> 3) & 1) * 8) * 2);

    int lrow = lane >> 2, lcol = (lane & 3) * 2;

    for (int g = 0; g < 3; g++) {
        {
            const uint4* sh = (const uint4*)(g_Bhi + g * 16384);
            const uint4* sl = (const uint4*)(g_Blo + g * 16384);
            for (int i = tid; i < 2048; i += 256) {
                int row = i >> 4, c = i & 15;
                int off = row * SROW + c * 16;
                *(uint4*)(smem + SM_B_HI + off) = sh[i];
                *(uint4*)(smem + SM_B_LO + off) = sl[i];
            }
        }
        __syncthreads();

        float acc[2][4][4];
        #pragma unroll
        for (int mt = 0; mt < 2; mt++)
            #pragma unroll
            for (int nt = 0; nt < 4; nt++)
                #pragma unroll
                for (int j = 0; j < 4; j++) acc[mt][nt][j] = 0.f;

        #pragma unroll
        for (int k = 0; k < 8; k++) {
            uint32_t ah[2][4], al[2][4];
            #pragma unroll
            for (int mt = 0; mt < 2; mt++) {
                ldx4(ah[mt], aAddr + mt * (16 * SROW) + k * 32);
                ldx4(al[mt], aAddr + mt * (16 * SROW) + k * 32 + (SM_A_LO - SM_A_HI));
            }
            #pragma unroll
            for (int nt = 0; nt < 4; nt++) {
                uint32_t bh[2], bl[2];
                uint32_t bo = bAddr + nt * (8 * SROW) + k * 32;
                ldx2(bh, bo);
                ldx2(bl, bo + (SM_B_LO - SM_B_HI));
                #pragma unroll
                for (int mt = 0; mt < 2; mt++) {
                    mma_bf16(acc[mt][nt], ah[mt], bh);
                    mma_bf16(acc[mt][nt], ah[mt], bl);
                    mma_bf16(acc[mt][nt], al[mt], bh);
                }
            }
        }
        __syncthreads();

        const float* bias = (g == 0) ? ba : (g == 2) ? bg : nullptr;
        float* base = (g == 0) ? g_P1 : g_T;
        int stride = (g == 0) ? 128 : 256;
        int coff = (g == 2) ? 128 : 0;

        #pragma unroll
        for (int mt = 0; mt < 2; mt++) {
            int r0 = rowBase + warpM * 32 + mt * 16 + lrow;
            int r1 = r0 + 8;
            #pragma unroll
            for (int nt = 0; nt < 4; nt++) {
                int n = warpN * 32 + nt * 8 + lcol;
                float b0 = 0.f, b1 = 0.f;
                if (bias) { b0 = __ldg(bias + n); b1 = __ldg(bias + n + 1); }
                if (r0 < NE) {
                    float2 v = make_float2(acc[mt][nt][0] + b0, acc[mt][nt][1] + b1);
                    *(float2*)(base + (long)r0 * stride + coff + n) = v;
                }
                if (r1 < NE) {
                    float2 v = make_float2(acc[mt][nt][2] + b0, acc[mt][nt][3] + b1);
                    *(float2*)(base + (long)r1 * stride + coff + n) = v;
                }
            }
        }
    }
}

// ---------------- fused edge kernel: dual-stream online softmax ----------------
struct Edge { float4 tlo, thi, ra, gr; };

__device__ __forceinline__ void fetch_edge(int idx, int lane, const float4* RG, Edge& E) {
    unsigned pk = __ldg(&g_elist[idx]);
    int h = pk & 0xFFFFu, r = pk >> 16;
    const float4* T4 = (const float4*)(g_T + (long)h * 256);
    E.tlo = __ldg(&T4[lane]);
    E.thi = __ldg(&T4[32 + lane]);
    E.ra  = __ldg(&RG[r * 64 + lane]);
    E.gr  = __ldg(&RG[r * 64 + 32 + lane]);
}

__device__ __forceinline__ void consume(const Edge& E, const float4& p1, const float4& av,
                                        float4& sA, float4& sG, float4& acc, float& m, float& s) {
    sA.x += E.ra.x; sA.y += E.ra.y; sA.z += E.ra.z; sA.w += E.ra.w;
    sG.x += E.gr.x; sG.y += E.gr.y; sG.z += E.gr.z; sG.w += E.gr.w;
    float hx = tanh_fast(p1.x + E.tlo.x + E.ra.x);
    float hy = tanh_fast(p1.y + E.tlo.y + E.ra.y);
    float hz = tanh_fast(p1.z + E.tlo.z + E.ra.z);
    float hw = tanh_fast(p1.w + E.tlo.w + E.ra.w);
    float part = hx * av.x + hy * av.y + hz * av.z + hw * av.w;
    part += __shfl_xor_sync(0xffffffffu, part, 1);
    part += __shfl_xor_sync(0xffffffffu, part, 2);
    float nm = fmaxf(m, part);
    float f = __expf(m - nm);
    float w = __expf(part - nm);
    s = s * f + w;
    acc.x = acc.x * f + w * (E.thi.x + E.gr.x);
    acc.y = acc.y * f + w * (E.thi.y + E.gr.y);
    acc.z = acc.z * f + w * (E.thi.z + E.gr.z);
    acc.w = acc.w * f + w * (E.thi.w + E.gr.w);
    m = nm;
}

__global__ __launch_bounds__(256) void k_main(const float* __restrict__ av_g,
                                              float* __restrict__ out) {
    int tid = threadIdx.x, lane = tid & 31, warp = tid >> 5;
    float4 av = ((const float4*)av_g)[lane];
    const float4* RG = (const float4*)g_RG;

    int gw = blockIdx.x * 8 + warp;
    int nw = gridDim.x * 8;
    for (int ent = gw; ent < NE; ent += nw) {
        int beg = g_rowptr[ent], end = g_rowptr[ent + 1];
        float4 p1 = *(const float4*)(g_P1 + (long)ent * 128 + lane * 4);
        float4 sA = make_float4(0.f, 0.f, 0.f, 0.f);
        float4 sG = sA;
        float4 acc1 = sA, acc2 = sA;
        float m1 = -1e30f, s1 = 0.f, m2 = -1e30f, s2 = 0.f;

        int deg = end - beg;
        int len1 = deg >> 1;           // stream1: [beg, beg+len1)
        int mid = beg + len1;          // stream2: [mid, end), len2 = deg - len1 >= len1

        Edge E1, E2;
        if (len1 > 0) fetch_edge(beg, lane, RG, E1);
        if (mid < end) fetch_edge(mid, lane, RG, E2);

        for (int t = 0; t < len1; t++) {
            Edge C1 = E1, C2 = E2;
            if (t + 1 < len1) fetch_edge(beg + t + 1, lane, RG, E1);
            if (mid + t + 1 < end) fetch_edge(mid + t + 1, lane, RG, E2);
            consume(C1, p1, av, sA, sG, acc1, m1, s1);
            consume(C2, p1, av, sA, sG, acc2, m2, s2);
        }
        if (deg - len1 > len1) {  // odd: one extra edge in stream2 (already prefetched)
            consume(E2, p1, av, sA, sG, acc2, m2, s2);
        }

        // merge stream states (exact)
        float M = fmaxf(m1, m2);
        float f1 = __expf(m1 - M), f2 = __expf(m2 - M);
        float s = s1 * f1 + s2 * f2;
        float4 acc = make_float4(acc1.x * f1 + acc2.x * f2,
                                 acc1.y * f1 + acc2.y * f2,
                                 acc1.z * f1 + acc2.z * f2,
                                 acc1.w * f1 + acc2.w * f2);
        float m = M;

        // self-loop edge: rel term = (sum Ra[rel]) / freq
        {
            float inv = (deg > 0) ? 1.f / (float)deg : 1.f;
            Edge Es;
            const float4* T4 = (const float4*)(g_T + (long)ent * 256);
            Es.tlo = __ldg(&T4[lane]);
            Es.thi = __ldg(&T4[32 + lane]);
            Es.ra = make_float4(sA.x * inv, sA.y * inv, sA.z * inv, sA.w * inv);
            Es.gr = make_float4(sG.x * inv, sG.y * inv, sG.z * inv, sG.w * inv);
            float4 dummyA = make_float4(0, 0, 0, 0), dummyG = dummyA;
            consume(Es, p1, av, dummyA, dummyG, acc, m, s);
        }
        float invs = 1.f / (s + 1e-16f);
        float4 o = make_float4(acc.x * invs, acc.y * invs, acc.z * invs, acc.w * invs);
        *(float4*)(out + (long)ent * 128 + lane * 4) = o;
    }
}

extern "C" void kernel_launch(void* const* d_in, const int* in_sizes, int n_in,
                              void* d_out, int out_size) {
    const float* emb_ent = (const float*)d_in[0];
    const float* emb_rel = (const float*)d_in[1];
    const int*   trip    = (const int*)d_in[2];
    const float* Wa      = (const float*)d_in[3];
    const float* ba      = (const float*)d_in[4];
    const float* av      = (const float*)d_in[5];
    const float* Wg      = (const float*)d_in[6];
    const float* bg      = (const float*)d_in[7];
    float* out = (float*)d_out;

    static cudaStream_t s2 = nullptr;
    static cudaEvent_t evFork = nullptr, evJoin = nullptr;
    if (!s2) {
        cudaStreamCreateWithFlags(&s2, cudaStreamNonBlocking);
        cudaEventCreateWithFlags(&evFork, cudaEventDisableTiming);
        cudaEventCreateWithFlags(&evJoin, cudaEventDisableTiming);
        cudaFuncSetAttribute(k_mmagemm, cudaFuncAttributeMaxDynamicSharedMemorySize, SM_TOTAL);
    }

    // fork: CSR chain + relgemm on s2, GEMM chain on s0, join before k_main.
    cudaEventRecord(evFork, 0);
    cudaStreamWaitEvent(s2, evFork, 0);

    k_relgemm<<<NR, 128, 0, s2>>>(emb_rel, Wa, Wg);                 // 1 (s2)
    k_zero<<<(NE + 1 + 255) / 256, 256, 0, s2>>>();                 // 2 (s2)
    k_prepB<<<(3 * 16384 + 255) / 256, 256>>>(Wa, Wg);              // 3 (s0)
    k_mmagemm<<<(NE + 63) / 64, 256, SM_TOTAL>>>(emb_ent, ba, bg);  // 4 (s0) <- profile target
    k_count<<<(NT + 255) / 256, 256, 0, s2>>>(trip);                // 5 (s2)
    k_scanA<<<NSCB, SCB, 0, s2>>>();                                // 6 (s2)
    k_scanB<<<1, 128, 0, s2>>>();                                   // 7 (s2)
    k_scanC<<<NSCB, SCB, 0, s2>>>();                                // 8 (s2)
    k_scatter<<<(NT + 255) / 256, 256, 0, s2>>>(trip);              // 9 (s2)
    cudaEventRecord(evJoin, s2);

    cudaStreamWaitEvent(0, evJoin, 0);
    k_main<<<1184, 256>>>(av, out);                                 // 10
}

// round 14
// speedup vs baseline: 1.0646x; 1.0646x over previous
#include <cuda_runtime.h>
#include <cuda_bf16.h>
#include <math.h>
#include <cstdint>

#define NE 50000
#define NR 64
#define NT 400000

typedef unsigned long long u64;

// Scratch (static __device__ — no runtime allocation)
__device__ float    g_T[NE * 256];    // [ent][0:128]=emb@Wa2 (head/att), [128:256]=emb@Wg1+bg (head/msg)
__device__ float    g_P1[NE * 128];   // emb@Wa1 + ba (tail/att)
__device__ float    g_RG[NR * 256];   // [rel][0:128]=emb_rel@Wa3, [128:256]=emb_rel@Wg2
__device__ int      g_rowptr[NE + 1];
__device__ int      g_cursor[NE];
__device__ unsigned g_elist[NT];      // head | (rel<<16)
__device__ int      g_bsum[128];
__device__ int      g_boff[128];
// Pre-transposed bf16 weight images: [group][n][k], group 0=Wa1, 1=Wa2, 2=Wg1
__device__ __align__(16) unsigned short g_Bhi[3 * 16384];
__device__ __align__(16) unsigned short g_Blo[3 * 16384];

// ==================== warp-MMA helpers (sm_80+ PTX, works on sm_103) ====================
__device__ __forceinline__ uint32_t smem_u32(const void* p) {
    uint32_t a;
    asm("{ .reg .u64 t; cvta.to.shared.u64 t, %1; cvt.u32.u64 %0, t; }" : "=r"(a) : "l"(p));
    return a;
}
__device__ __forceinline__ void ldx4(uint32_t r[4], uint32_t addr) {
    asm volatile("ldmatrix.sync.aligned.m8n8.x4.shared.b16 {%0,%1,%2,%3}, [%4];"
                 : "=r"(r[0]), "=r"(r[1]), "=r"(r[2]), "=r"(r[3]) : "r"(addr));
}
__device__ __forceinline__ void mma_bf16(float d[4], const uint32_t a[4], const uint32_t* b) {
    asm volatile("mma.sync.aligned.m16n8k16.row.col.f32.bf16.bf16.f32 "
                 "{%0,%1,%2,%3}, {%4,%5,%6,%7}, {%8,%9}, {%0,%1,%2,%3};"
                 : "+f"(d[0]), "+f"(d[1]), "+f"(d[2]), "+f"(d[3])
                 : "r"(a[0]), "r"(a[1]), "r"(a[2]), "r"(a[3]), "r"(b[0]), "r"(b[1]));
}
__device__ __forceinline__ float tanh_fast(float x) {
    float y; asm("tanh.approx.f32 %0, %1;" : "=f"(y) : "f"(x)); return y;
}

// ---------------- CSR build ----------------
__global__ void k_zero() {
    int i = blockIdx.x * blockDim.x + threadIdx.x;
    if (i <= NE) g_rowptr[i] = 0;
}

__global__ void k_count(const int* __restrict__ trip) {
    int e = blockIdx.x * blockDim.x + threadIdx.x;
    if (e < NT) atomicAdd(&g_rowptr[trip[3 * e + 2]], 1);
}

// 3-stage parallel scan
#define SCB 512
#define NSCB ((NE + SCB - 1) / SCB)   // 98

__global__ void k_scanA() {
    __shared__ int wsum[16];
    int b = blockIdx.x, t = threadIdx.x, lane = t & 31, w = t >> 5;
    int idx = b * SCB + t;
    int v = (idx < NE) ? g_rowptr[idx] : 0;
    #pragma unroll
    for (int o = 16; o > 0; o >>= 1) v += __shfl_down_sync(0xffffffffu, v, o);
    if (lane == 0) wsum[w] = v;
    __syncthreads();
    if (t == 0) {
        int s = 0;
        #pragma unroll
        for (int i = 0; i < 16; i++) s += wsum[i];
        g_bsum[b] = s;
    }
}

__global__ void k_scanB() {
    __shared__ int woff[4];
    int t = threadIdx.x, lane = t & 31, w = t >> 5;
    int v = (t < NSCB) ? g_bsum[t] : 0;
    int incl = v;
    #pragma unroll
    for (int o = 1; o < 32; o <<= 1) {
        int u = __shfl_up_sync(0xffffffffu, incl, o);
        if (lane >= o) incl += u;
    }
    if (lane == 31) woff[w] = incl;
    __syncthreads();
    int base = 0;
    for (int i = 0; i < w; i++) base += woff[i];
    if (t < NSCB) g_boff[t] = base + incl - v;
    if (t == 0) g_rowptr[NE] = NT;
}

__global__ void k_scanC() {
    __shared__ int wsum[16];
    int b = blockIdx.x, t = threadIdx.x, lane = t & 31, w = t >> 5;
    int idx = b * SCB + t;
    int v = (idx < NE) ? g_rowptr[idx] : 0;
    int incl = v;
    #pragma unroll
    for (int o = 1; o < 32; o <<= 1) {
        int u = __shfl_up_sync(0xffffffffu, incl, o);
        if (lane >= o) incl += u;
    }
    if (lane == 31) wsum[w] = incl;
    __syncthreads();
    if (w == 0 && lane < 16) {
        int x = wsum[lane];
        #pragma unroll
        for (int o = 1; o < 16; o <<= 1) {
            int u = __shfl_up_sync(0xffffu, x, o);
            if (lane >= o) x += u;
        }
        wsum[lane] = x;
    }
    __syncthreads();
    int excl = g_boff[b] + (w > 0 ? wsum[w - 1] : 0) + (incl - v);
    if (idx < NE) { g_rowptr[idx] = excl; g_cursor[idx] = excl; }
}

__global__ void k_scatter(const int* __restrict__ trip) {
    int e = blockIdx.x * blockDim.x + threadIdx.x;
    if (e < NT) {
        int h = trip[3 * e], r = trip[3 * e + 1], t = trip[3 * e + 2];
        int pos = atomicAdd(&g_cursor[t], 1);
        g_elist[pos] = (unsigned)h | ((unsigned)r << 16);
    }
}

// ---------------- weight prep: fp32 -> hi/lo bf16, transposed to [n][k] ----------------
__global__ void k_prepB(const float* __restrict__ Wa, const float* __restrict__ Wg) {
    int idx = blockIdx.x * blockDim.x + threadIdx.x;
    if (idx >= 3 * 16384) return;
    int g = idx >> 14, rem = idx & 16383;
    int n = rem >> 7, k = rem & 127;
    float w = (g == 0) ? Wa[k * 128 + n] : (g == 1) ? Wa[(128 + k) * 128 + n] : Wg[k * 128 + n];
    __nv_bfloat16 hi = __float2bfloat16(w);
    __nv_bfloat16 lo = __float2bfloat16(w - __bfloat162float(hi));
    unsigned short hb, lb;
    memcpy(&hb, &hi, 2); memcpy(&lb, &lo, 2);
    g_Bhi[idx] = hb;
    g_Blo[idx] = lb;
}

// ---------------- relation GEMM, MLP-optimized ----------------
__global__ __launch_bounds__(128) void k_relgemm(const float* __restrict__ emb_rel,
                                                 const float* __restrict__ Wa,
                                                 const float* __restrict__ Wg) {
    __shared__ float er[128];
    int r = blockIdx.x;
    int tid = threadIdx.x;  // 128 threads
    er[tid] = emb_rel[r * 128 + tid];
    __syncthreads();
    int half = tid >> 6;          // 0: Wa-att, 1: Wg-msg
    int j0 = (tid & 63) * 2;      // 2 columns per thread
    const float* W = half ? (Wg + 128 * 128) : (Wa + 256 * 128);
    float ax = 0.f, ay = 0.f;
    #pragma unroll 16
    for (int k = 0; k < 128; k++) {
        float e = er[k];
        float2 w = __ldg((const float2*)(W + k * 128 + j0));
        ax += e * w.x;
        ay += e * w.y;
    }
    float2 o = make_float2(ax, ay);
    *(float2*)(g_RG + r * 256 + half * 128 + j0) = o;
}

// ---------------- HMMA entity GEMM: block M64, 6 B-stages of N64, bf16 hi/lo 3-pass ----------------
// smem 69632B -> 3 blocks/SM (24 warps). Warp grid 2x4 (32 rows x 16 cols each).
#define SROW 272
#define SM_A_HI 0
#define SM_A_LO 17408
#define SM_B_HI 34816
#define SM_B_LO 52224
#define SM_TOTAL 69632

__global__ __launch_bounds__(256, 3) void k_mmagemm(const float* __restrict__ A,
                                                    const float* __restrict__ ba,
                                                    const float* __restrict__ bg) {
    extern __shared__ char smem[];
    uint32_t sb = smem_u32(smem);
    int tid = threadIdx.x, wid = tid >> 5, lane = tid & 31;
    int rowBase = blockIdx.x * 64;
    int warpM = wid & 1, warpN = wid >> 1;  // 2x4: warp tile 32 rows x 16 cols

    // ---- fill A once (fp32 -> bf16 hi/lo): 64 rows x 128 k ----
    for (int i = tid; i < 2048; i += 256) {
        int m = i >> 5, k4 = (i & 31) * 4;
        int gr = rowBase + m;
        float4 v = make_float4(0.f, 0.f, 0.f, 0.f);
        if (gr < NE) v = *(const float4*)(A + (long)gr * 128 + k4);
        __nv_bfloat16 h0 = __float2bfloat16(v.x), h1 = __float2bfloat16(v.y);
        __nv_bfloat16 h2 = __float2bfloat16(v.z), h3 = __float2bfloat16(v.w);
        __nv_bfloat16 l0 = __float2bfloat16(v.x - __bfloat162float(h0));
        __nv_bfloat16 l1 = __float2bfloat16(v.y - __bfloat162float(h1));
        __nv_bfloat16 l2 = __float2bfloat16(v.z - __bfloat162float(h2));
        __nv_bfloat16 l3 = __float2bfloat16(v.w - __bfloat162float(h3));
        int off = m * SROW + k4 * 2;
        __nv_bfloat162 hv0; hv0.x = h0; hv0.y = h1;
        __nv_bfloat162 hv1; hv1.x = h2; hv1.y = h3;
        __nv_bfloat162 lv0; lv0.x = l0; lv0.y = l1;
        __nv_bfloat162 lv1; lv1.x = l2; lv1.y = l3;
        *(__nv_bfloat162*)(smem + SM_A_HI + off) = hv0;
        *(__nv_bfloat162*)(smem + SM_A_HI + off + 4) = hv1;
        *(__nv_bfloat162*)(smem + SM_A_LO + off) = lv0;
        *(__nv_bfloat162*)(smem + SM_A_LO + off + 4) = lv1;
    }

    // A fragment base (x4: lanes 0-15 rows, 16-31 k+8)
    uint32_t aAddr = sb + SM_A_HI + (uint32_t)((warpM * 32 + (lane & 15)) * SROW + ((lane >> 4) * 8) * 2);
    // B fragment base (x4 over 2 n8-frags: lanes 0-7 n-lo/k-lo, 8-15 n-lo/k-hi, 16-23 n-hi/k-lo, 24-31 n-hi/k-hi)
    uint32_t bAddr = sb + SM_B_HI + (uint32_t)((warpN * 16 + (lane & 7) + ((lane >> 4) << 3)) * SROW
                                               + ((lane >> 3) & 1) * 16);

    int lrow = lane >> 2, lcol = (lane & 3) * 2;

    for (int stage = 0; stage < 6; stage++) {
        int g = stage >> 1, nhalf = stage & 1;
        // ---- fill B stage: 64 rows (n) x 128 k, hi/lo ----
        {
            const uint4* sh = (const uint4*)(g_Bhi + g * 16384 + nhalf * 8192);
            const uint4* sl = (const uint4*)(g_Blo + g * 16384 + nhalf * 8192);
            for (int i = tid; i < 1024; i += 256) {
                int row = i >> 4, c = i & 15;
                int off = row * SROW + c * 16;
                *(uint4*)(smem + SM_B_HI + off) = sh[i];
                *(uint4*)(smem + SM_B_LO + off) = sl[i];
            }
        }
        __syncthreads();

        float acc[2][2][4];
        #pragma unroll
        for (int mt = 0; mt < 2; mt++)
            #pragma unroll
            for (int nt = 0; nt < 2; nt++)
                #pragma unroll
                for (int j = 0; j < 4; j++) acc[mt][nt][j] = 0.f;

        #pragma unroll
        for (int k = 0; k < 8; k++) {
            uint32_t ah[2][4], al[2][4];
            #pragma unroll
            for (int mt = 0; mt < 2; mt++) {
                ldx4(ah[mt], aAddr + mt * (16 * SROW) + k * 32);
                ldx4(al[mt], aAddr + mt * (16 * SROW) + k * 32 + (SM_A_LO - SM_A_HI));
            }
            uint32_t bh[4], bl[4];
            ldx4(bh, bAddr + k * 32);
            ldx4(bl, bAddr + k * 32 + (SM_B_LO - SM_B_HI));
            #pragma unroll
            for (int nt = 0; nt < 2; nt++) {
                #pragma unroll
                for (int mt = 0; mt < 2; mt++) {
                    mma_bf16(acc[mt][nt], ah[mt], bh + 2 * nt);
                    mma_bf16(acc[mt][nt], ah[mt], bl + 2 * nt);
                    mma_bf16(acc[mt][nt], al[mt], bh + 2 * nt);
                }
            }
        }
        __syncthreads();  // done reading B before next stage overwrite

        // ---- epilogue for this stage ----
        const float* bias = (g == 0) ? ba : (g == 2) ? bg : nullptr;
        float* base = (g == 0) ? g_P1 : g_T;
        int stride = (g == 0) ? 128 : 256;
        int coff = (g == 2) ? 128 : 0;

        #pragma unroll
        for (int mt = 0; mt < 2; mt++) {
            int r0 = rowBase + warpM * 32 + mt * 16 + lrow;
            int r1 = r0 + 8;
            #pragma unroll
            for (int nt = 0; nt < 2; nt++) {
                int n = nhalf * 64 + warpN * 16 + nt * 8 + lcol;
                float b0 = 0.f, b1 = 0.f;
                if (bias) { b0 = __ldg(bias + n); b1 = __ldg(bias + n + 1); }
                if (r0 < NE) {
                    float2 v = make_float2(acc[mt][nt][0] + b0, acc[mt][nt][1] + b1);
                    *(float2*)(base + (long)r0 * stride + coff + n) = v;
                }
                if (r1 < NE) {
                    float2 v = make_float2(acc[mt][nt][2] + b0, acc[mt][nt][3] + b1);
                    *(float2*)(base + (long)r1 * stride + coff + n) = v;
                }
            }
        }
    }
}

// ---------------- fused edge kernel: pair-pipelined online softmax (R10 version) ----------------
struct Edge { float4 tlo, thi, ra, gr; };

__device__ __forceinline__ void fetch_edge(int idx, int lane, const float4* RG, Edge& E) {
    unsigned pk = __ldg(&g_elist[idx]);
    int h = pk & 0xFFFFu, r = pk >> 16;
    const float4* T4 = (const float4*)(g_T + (long)h * 256);
    E.tlo = __ldg(&T4[lane]);
    E.thi = __ldg(&T4[32 + lane]);
    E.ra  = __ldg(&RG[r * 64 + lane]);
    E.gr  = __ldg(&RG[r * 64 + 32 + lane]);
}

__device__ __forceinline__ void consume(const Edge& E, const float4& p1, const float4& av,
                                        float4& sA, float4& sG, float4& acc, float& m, float& s) {
    sA.x += E.ra.x; sA.y += E.ra.y; sA.z += E.ra.z; sA.w += E.ra.w;
    sG.x += E.gr.x; sG.y += E.gr.y; sG.z += E.gr.z; sG.w += E.gr.w;
    float hx = tanh_fast(p1.x + E.tlo.x + E.ra.x);
    float hy = tanh_fast(p1.y + E.tlo.y + E.ra.y);
    float hz = tanh_fast(p1.z + E.tlo.z + E.ra.z);
    float hw = tanh_fast(p1.w + E.tlo.w + E.ra.w);
    float part = hx * av.x + hy * av.y + hz * av.z + hw * av.w;
    part += __shfl_xor_sync(0xffffffffu, part, 1);
    part += __shfl_xor_sync(0xffffffffu, part, 2);
    float nm = fmaxf(m, part);
    float f = __expf(m - nm);
    float w = __expf(part - nm);
    s = s * f + w;
    acc.x = acc.x * f + w * (E.thi.x + E.gr.x);
    acc.y = acc.y * f + w * (E.thi.y + E.gr.y);
    acc.z = acc.z * f + w * (E.thi.z + E.gr.z);
    acc.w = acc.w * f + w * (E.thi.w + E.gr.w);
    m = nm;
}

__global__ __launch_bounds__(256) void k_main(const float* __restrict__ av_g,
                                              float* __restrict__ out) {
    int tid = threadIdx.x, lane = tid & 31, warp = tid >> 5;
    float4 av = ((const float4*)av_g)[lane];
    const float4* RG = (const float4*)g_RG;

    int gw = blockIdx.x * 8 + warp;
    int nw = gridDim.x * 8;
    for (int ent = gw; ent < NE; ent += nw) {
        int beg = g_rowptr[ent], end = g_rowptr[ent + 1];
        float4 p1 = *(const float4*)(g_P1 + (long)ent * 128 + lane * 4);
        float4 sA = make_float4(0.f, 0.f, 0.f, 0.f);
        float4 sG = sA, acc = sA;
        float m = -1e30f, s = 0.f;

        int deg = end - beg;
        int end2 = beg + (deg & ~1);  // paired portion

        Edge E0, E1;
        if (beg < end2) { fetch_edge(beg, lane, RG, E0); fetch_edge(beg + 1, lane, RG, E1); }
        for (int i = beg; i < end2; i += 2) {
            Edge C0 = E0, C1 = E1;
            if (i + 3 < end2 + 1) {
                fetch_edge(i + 2, lane, RG, E0);
                fetch_edge(i + 3, lane, RG, E1);
            }
            consume(C0, p1, av, sA, sG, acc, m, s);
            consume(C1, p1, av, sA, sG, acc, m, s);
        }
        if (end2 < end) {  // odd tail edge
            Edge Et;
            fetch_edge(end2, lane, RG, Et);
            consume(Et, p1, av, sA, sG, acc, m, s);
        }

        // self-loop edge: rel term = (sum Ra[rel]) / freq
        {
            float inv = (deg > 0) ? 1.f / (float)deg : 1.f;
            Edge Es;
            const float4* T4 = (const float4*)(g_T + (long)ent * 256);
            Es.tlo = __ldg(&T4[lane]);
            Es.thi = __ldg(&T4[32 + lane]);
            Es.ra = make_float4(sA.x * inv, sA.y * inv, sA.z * inv, sA.w * inv);
            Es.gr = make_float4(sG.x * inv, sG.y * inv, sG.z * inv, sG.w * inv);
            float4 dummyA = make_float4(0, 0, 0, 0), dummyG = dummyA;
            consume(Es, p1, av, dummyA, dummyG, acc, m, s);
        }
        float invs = 1.f / (s + 1e-16f);
        float4 o = make_float4(acc.x * invs, acc.y * invs, acc.z * invs, acc.w * invs);
        *(float4*)(out + (long)ent * 128 + lane * 4) = o;
    }
}

extern "C" void kernel_launch(void* const* d_in, const int* in_sizes, int n_in,
                              void* d_out, int out_size) {
    const float* emb_ent = (const float*)d_in[0];
    const float* emb_rel = (const float*)d_in[1];
    const int*   trip    = (const int*)d_in[2];
    const float* Wa      = (const float*)d_in[3];
    const float* ba      = (const float*)d_in[4];
    const float* av      = (const float*)d_in[5];
    const float* Wg      = (const float*)d_in[6];
    const float* bg      = (const float*)d_in[7];
    float* out = (float*)d_out;

    static cudaStream_t s2 = nullptr;
    static cudaEvent_t evFork = nullptr, evJoin = nullptr;
    if (!s2) {
        cudaStreamCreateWithFlags(&s2, cudaStreamNonBlocking);
        cudaEventCreateWithFlags(&evFork, cudaEventDisableTiming);
        cudaEventCreateWithFlags(&evJoin, cudaEventDisableTiming);
        cudaFuncSetAttribute(k_mmagemm, cudaFuncAttributeMaxDynamicSharedMemorySize, SM_TOTAL);
    }

    // fork: CSR chain + relgemm on s2, GEMM chain on s0, join before k_main.
    cudaEventRecord(evFork, 0);
    cudaStreamWaitEvent(s2, evFork, 0);

    k_relgemm<<<NR, 128, 0, s2>>>(emb_rel, Wa, Wg);                 // 1 (s2)
    k_zero<<<(NE + 1 + 255) / 256, 256, 0, s2>>>();                 // 2 (s2)
    k_prepB<<<(3 * 16384 + 255) / 256, 256>>>(Wa, Wg);              // 3 (s0)
    k_mmagemm<<<(NE + 63) / 64, 256, SM_TOTAL>>>(emb_ent, ba, bg);  // 4 (s0) <- profile target
    k_count<<<(NT + 255) / 256, 256, 0, s2>>>(trip);                // 5 (s2)
    k_scanA<<<NSCB, SCB, 0, s2>>>();                                // 6 (s2)
    k_scanB<<<1, 128, 0, s2>>>();                                   // 7 (s2)
    k_scanC<<<NSCB, SCB, 0, s2>>>();                                // 8 (s2)
    k_scatter<<<(NT + 255) / 256, 256, 0, s2>>>(trip);              // 9 (s2)
    cudaEventRecord(evJoin, s2);

    cudaStreamWaitEvent(0, evJoin, 0);
    k_main<<<1184, 256>>>(av, out);                                 // 10
}

// round 15
// speedup vs baseline: 1.0753x; 1.0100x over previous
#include <cuda_runtime.h>
#include <cuda_bf16.h>
#include <cuda_fp16.h>
#include <math.h>
#include <cstdint>

#define NE 50000
#define NR 64
#define NT 400000

typedef unsigned long long u64;

// Scratch (static __device__ — no runtime allocation)
// g_Th: fp16 head table, lane-interleaved: [ent][lane][0:4]=att ch 4*lane.., [4:8]=msg ch 4*lane..
__device__ __align__(16) __half g_Th[NE * 256];
__device__ float    g_P1[NE * 128];   // emb@Wa1 + ba (tail/att), fp32
__device__ float    g_RG[NR * 256];   // [rel][0:128]=emb_rel@Wa3, [128:256]=emb_rel@Wg2
__device__ int      g_rowptr[NE + 1];
__device__ int      g_cursor[NE];
__device__ unsigned g_elist[NT];      // head | (rel<<16)
__device__ int      g_bsum[128];
__device__ int      g_boff[128];
// Pre-transposed bf16 weight images: [group][n][k], group 0=Wa1, 1=Wa2, 2=Wg1
__device__ __align__(16) unsigned short g_Bhi[3 * 16384];
__device__ __align__(16) unsigned short g_Blo[3 * 16384];

// ==================== warp-MMA helpers (sm_80+ PTX, works on sm_103) ====================
__device__ __forceinline__ uint32_t smem_u32(const void* p) {
    uint32_t a;
    asm("{ .reg .u64 t; cvta.to.shared.u64 t, %1; cvt.u32.u64 %0, t; }" : "=r"(a) : "l"(p));
    return a;
}
__device__ __forceinline__ void ldx4(uint32_t r[4], uint32_t addr) {
    asm volatile("ldmatrix.sync.aligned.m8n8.x4.shared.b16 {%0,%1,%2,%3}, [%4];"
                 : "=r"(r[0]), "=r"(r[1]), "=r"(r[2]), "=r"(r[3]) : "r"(addr));
}
__device__ __forceinline__ void mma_bf16(float d[4], const uint32_t a[4], const uint32_t* b) {
    asm volatile("mma.sync.aligned.m16n8k16.row.col.f32.bf16.bf16.f32 "
                 "{%0,%1,%2,%3}, {%4,%5,%6,%7}, {%8,%9}, {%0,%1,%2,%3};"
                 : "+f"(d[0]), "+f"(d[1]), "+f"(d[2]), "+f"(d[3])
                 : "r"(a[0]), "r"(a[1]), "r"(a[2]), "r"(a[3]), "r"(b[0]), "r"(b[1]));
}
__device__ __forceinline__ float tanh_fast(float x) {
    float y; asm("tanh.approx.f32 %0, %1;" : "=f"(y) : "f"(x)); return y;
}

// ---------------- CSR build ----------------
__global__ void k_zero() {
    int i = blockIdx.x * blockDim.x + threadIdx.x;
    if (i <= NE) g_rowptr[i] = 0;
}

__global__ void k_count(const int* __restrict__ trip) {
    int e = blockIdx.x * blockDim.x + threadIdx.x;
    if (e < NT) atomicAdd(&g_rowptr[trip[3 * e + 2]], 1);
}

// 3-stage parallel scan
#define SCB 512
#define NSCB ((NE + SCB - 1) / SCB)   // 98

__global__ void k_scanA() {
    __shared__ int wsum[16];
    int b = blockIdx.x, t = threadIdx.x, lane = t & 31, w = t >> 5;
    int idx = b * SCB + t;
    int v = (idx < NE) ? g_rowptr[idx] : 0;
    #pragma unroll
    for (int o = 16; o > 0; o >>= 1) v += __shfl_down_sync(0xffffffffu, v, o);
    if (lane == 0) wsum[w] = v;
    __syncthreads();
    if (t == 0) {
        int s = 0;
        #pragma unroll
        for (int i = 0; i < 16; i++) s += wsum[i];
        g_bsum[b] = s;
    }
}

__global__ void k_scanB() {
    __shared__ int woff[4];
    int t = threadIdx.x, lane = t & 31, w = t >> 5;
    int v = (t < NSCB) ? g_bsum[t] : 0;
    int incl = v;
    #pragma unroll
    for (int o = 1; o < 32; o <<= 1) {
        int u = __shfl_up_sync(0xffffffffu, incl, o);
        if (lane >= o) incl += u;
    }
    if (lane == 31) woff[w] = incl;
    __syncthreads();
    int base = 0;
    for (int i = 0; i < w; i++) base += woff[i];
    if (t < NSCB) g_boff[t] = base + incl - v;
    if (t == 0) g_rowptr[NE] = NT;
}

__global__ void k_scanC() {
    __shared__ int wsum[16];
    int b = blockIdx.x, t = threadIdx.x, lane = t & 31, w = t >> 5;
    int idx = b * SCB + t;
    int v = (idx < NE) ? g_rowptr[idx] : 0;
    int incl = v;
    #pragma unroll
    for (int o = 1; o < 32; o <<= 1) {
        int u = __shfl_up_sync(0xffffffffu, incl, o);
        if (lane >= o) incl += u;
    }
    if (lane == 31) wsum[w] = incl;
    __syncthreads();
    if (w == 0 && lane < 16) {
        int x = wsum[lane];
        #pragma unroll
        for (int o = 1; o < 16; o <<= 1) {
            int u = __shfl_up_sync(0xffffu, x, o);
            if (lane >= o) x += u;
        }
        wsum[lane] = x;
    }
    __syncthreads();
    int excl = g_boff[b] + (w > 0 ? wsum[w - 1] : 0) + (incl - v);
    if (idx < NE) { g_rowptr[idx] = excl; g_cursor[idx] = excl; }
}

__global__ void k_scatter(const int* __restrict__ trip) {
    int e = blockIdx.x * blockDim.x + threadIdx.x;
    if (e < NT) {
        int h = trip[3 * e], r = trip[3 * e + 1], t = trip[3 * e + 2];
        int pos = atomicAdd(&g_cursor[t], 1);
        g_elist[pos] = (unsigned)h | ((unsigned)r << 16);
    }
}

// ---------------- weight prep: fp32 -> hi/lo bf16, transposed to [n][k] ----------------
__global__ void k_prepB(const float* __restrict__ Wa, const float* __restrict__ Wg) {
    int idx = blockIdx.x * blockDim.x + threadIdx.x;
    if (idx >= 3 * 16384) return;
    int g = idx >> 14, rem = idx & 16383;
    int n = rem >> 7, k = rem & 127;
    float w = (g == 0) ? Wa[k * 128 + n] : (g == 1) ? Wa[(128 + k) * 128 + n] : Wg[k * 128 + n];
    __nv_bfloat16 hi = __float2bfloat16(w);
    __nv_bfloat16 lo = __float2bfloat16(w - __bfloat162float(hi));
    unsigned short hb, lb;
    memcpy(&hb, &hi, 2); memcpy(&lb, &lo, 2);
    g_Bhi[idx] = hb;
    g_Blo[idx] = lb;
}

// ---------------- relation GEMM, MLP-optimized ----------------
__global__ __launch_bounds__(128) void k_relgemm(const float* __restrict__ emb_rel,
                                                 const float* __restrict__ Wa,
                                                 const float* __restrict__ Wg) {
    __shared__ float er[128];
    int r = blockIdx.x;
    int tid = threadIdx.x;  // 128 threads
    er[tid] = emb_rel[r * 128 + tid];
    __syncthreads();
    int half = tid >> 6;          // 0: Wa-att, 1: Wg-msg
    int j0 = (tid & 63) * 2;      // 2 columns per thread
    const float* W = half ? (Wg + 128 * 128) : (Wa + 256 * 128);
    float ax = 0.f, ay = 0.f;
    #pragma unroll 16
    for (int k = 0; k < 128; k++) {
        float e = er[k];
        float2 w = __ldg((const float2*)(W + k * 128 + j0));
        ax += e * w.x;
        ay += e * w.y;
    }
    float2 o = make_float2(ax, ay);
    *(float2*)(g_RG + r * 256 + half * 128 + j0) = o;
}

// ---------------- HMMA entity GEMM: block M64, 6 B-stages of N64, bf16 hi/lo 3-pass ----------------
// Epilogue: g=0 -> fp32 g_P1; g=1 (att) / g=2 (msg) -> fp16 lane-interleaved g_Th.
#define SROW 272
#define SM_A_HI 0
#define SM_A_LO 17408
#define SM_B_HI 34816
#define SM_B_LO 52224
#define SM_TOTAL 69632

__global__ __launch_bounds__(256, 3) void k_mmagemm(const float* __restrict__ A,
                                                    const float* __restrict__ ba,
                                                    const float* __restrict__ bg) {
    extern __shared__ char smem[];
    uint32_t sb = smem_u32(smem);
    int tid = threadIdx.x, wid = tid >> 5, lane = tid & 31;
    int rowBase = blockIdx.x * 64;
    int warpM = wid & 1, warpN = wid >> 1;  // 2x4: warp tile 32 rows x 16 cols

    // ---- fill A once (fp32 -> bf16 hi/lo): 64 rows x 128 k ----
    for (int i = tid; i < 2048; i += 256) {
        int m = i >> 5, k4 = (i & 31) * 4;
        int gr = rowBase + m;
        float4 v = make_float4(0.f, 0.f, 0.f, 0.f);
        if (gr < NE) v = *(const float4*)(A + (long)gr * 128 + k4);
        __nv_bfloat16 h0 = __float2bfloat16(v.x), h1 = __float2bfloat16(v.y);
        __nv_bfloat16 h2 = __float2bfloat16(v.z), h3 = __float2bfloat16(v.w);
        __nv_bfloat16 l0 = __float2bfloat16(v.x - __bfloat162float(h0));
        __nv_bfloat16 l1 = __float2bfloat16(v.y - __bfloat162float(h1));
        __nv_bfloat16 l2 = __float2bfloat16(v.z - __bfloat162float(h2));
        __nv_bfloat16 l3 = __float2bfloat16(v.w - __bfloat162float(h3));
        int off = m * SROW + k4 * 2;
        __nv_bfloat162 hv0; hv0.x = h0; hv0.y = h1;
        __nv_bfloat162 hv1; hv1.x = h2; hv1.y = h3;
        __nv_bfloat162 lv0; lv0.x = l0; lv0.y = l1;
        __nv_bfloat162 lv1; lv1.x = l2; lv1.y = l3;
        *(__nv_bfloat162*)(smem + SM_A_HI + off) = hv0;
        *(__nv_bfloat162*)(smem + SM_A_HI + off + 4) = hv1;
        *(__nv_bfloat162*)(smem + SM_A_LO + off) = lv0;
        *(__nv_bfloat162*)(smem + SM_A_LO + off + 4) = lv1;
    }

    uint32_t aAddr = sb + SM_A_HI + (uint32_t)((warpM * 32 + (lane & 15)) * SROW + ((lane >> 4) * 8) * 2);
    uint32_t bAddr = sb + SM_B_HI + (uint32_t)((warpN * 16 + (lane & 7) + ((lane >> 4) << 3)) * SROW
                                               + ((lane >> 3) & 1) * 16);

    int lrow = lane >> 2, lcol = (lane & 3) * 2;

    for (int stage = 0; stage < 6; stage++) {
        int g = stage >> 1, nhalf = stage & 1;
        {
            const uint4* sh = (const uint4*)(g_Bhi + g * 16384 + nhalf * 8192);
            const uint4* sl = (const uint4*)(g_Blo + g * 16384 + nhalf * 8192);
            for (int i = tid; i < 1024; i += 256) {
                int row = i >> 4, c = i & 15;
                int off = row * SROW + c * 16;
                *(uint4*)(smem + SM_B_HI + off) = sh[i];
                *(uint4*)(smem + SM_B_LO + off) = sl[i];
            }
        }
        __syncthreads();

        float acc[2][2][4];
        #pragma unroll
        for (int mt = 0; mt < 2; mt++)
            #pragma unroll
            for (int nt = 0; nt < 2; nt++)
                #pragma unroll
                for (int j = 0; j < 4; j++) acc[mt][nt][j] = 0.f;

        #pragma unroll
        for (int k = 0; k < 8; k++) {
            uint32_t ah[2][4], al[2][4];
            #pragma unroll
            for (int mt = 0; mt < 2; mt++) {
                ldx4(ah[mt], aAddr + mt * (16 * SROW) + k * 32);
                ldx4(al[mt], aAddr + mt * (16 * SROW) + k * 32 + (SM_A_LO - SM_A_HI));
            }
            uint32_t bh[4], bl[4];
            ldx4(bh, bAddr + k * 32);
            ldx4(bl, bAddr + k * 32 + (SM_B_LO - SM_B_HI));
            #pragma unroll
            for (int nt = 0; nt < 2; nt++) {
                #pragma unroll
                for (int mt = 0; mt < 2; mt++) {
                    mma_bf16(acc[mt][nt], ah[mt], bh + 2 * nt);
                    mma_bf16(acc[mt][nt], ah[mt], bl + 2 * nt);
                    mma_bf16(acc[mt][nt], al[mt], bh + 2 * nt);
                }
            }
        }
        __syncthreads();

        // ---- epilogue for this stage ----
        const float* bias = (g == 0) ? ba : (g == 2) ? bg : nullptr;

        #pragma unroll
        for (int mt = 0; mt < 2; mt++) {
            int r0 = rowBase + warpM * 32 + mt * 16 + lrow;
            int r1 = r0 + 8;
            #pragma unroll
            for (int nt = 0; nt < 2; nt++) {
                int n = nhalf * 64 + warpN * 16 + nt * 8 + lcol;  // 0..127, even
                float b0 = 0.f, b1 = 0.f;
                if (bias) { b0 = __ldg(bias + n); b1 = __ldg(bias + n + 1); }
                float v00 = acc[mt][nt][0] + b0, v01 = acc[mt][nt][1] + b1;
                float v10 = acc[mt][nt][2] + b0, v11 = acc[mt][nt][3] + b1;
                if (g == 0) {
                    if (r0 < NE) *(float2*)(g_P1 + (long)r0 * 128 + n) = make_float2(v00, v01);
                    if (r1 < NE) *(float2*)(g_P1 + (long)r1 * 128 + n) = make_float2(v10, v11);
                } else {
                    // lane-interleaved fp16: idx = ent*256 + (n>>2)*8 + (g==2?4:0) + (n&3)
                    int hoff = (n >> 2) * 8 + ((g == 2) ? 4 : 0) + (n & 3);
                    if (r0 < NE) *(__half2*)(g_Th + (long)r0 * 256 + hoff) = __floats2half2_rn(v00, v01);
                    if (r1 < NE) *(__half2*)(g_Th + (long)r1 * 256 + hoff) = __floats2half2_rn(v10, v11);
                }
            }
        }
    }
}

// ---------------- fused edge kernel: pair-pipelined online softmax, fp16 T gathers ----------------
struct Edge { float4 tlo, thi, ra, gr; };

__device__ __forceinline__ void unpack_T(uint4 t, float4& tlo, float4& thi) {
    float2 a0 = __half22float2(*(__half2*)&t.x);
    float2 a1 = __half22float2(*(__half2*)&t.y);
    float2 m0 = __half22float2(*(__half2*)&t.z);
    float2 m1 = __half22float2(*(__half2*)&t.w);
    tlo = make_float4(a0.x, a0.y, a1.x, a1.y);
    thi = make_float4(m0.x, m0.y, m1.x, m1.y);
}

__device__ __forceinline__ void fetch_edge(int idx, int lane, const float4* RG, Edge& E) {
    unsigned pk = __ldg(&g_elist[idx]);
    int h = pk & 0xFFFFu, r = pk >> 16;
    uint4 t = __ldg((const uint4*)(g_Th + (long)h * 256 + lane * 8));
    unpack_T(t, E.tlo, E.thi);
    E.ra  = __ldg(&RG[r * 64 + lane]);
    E.gr  = __ldg(&RG[r * 64 + 32 + lane]);
}

__device__ __forceinline__ void consume(const Edge& E, const float4& p1, const float4& av,
                                        float4& sA, float4& sG, float4& acc, float& m, float& s) {
    sA.x += E.ra.x; sA.y += E.ra.y; sA.z += E.ra.z; sA.w += E.ra.w;
    sG.x += E.gr.x; sG.y += E.gr.y; sG.z += E.gr.z; sG.w += E.gr.w;
    float hx = tanh_fast(p1.x + E.tlo.x + E.ra.x);
    float hy = tanh_fast(p1.y + E.tlo.y + E.ra.y);
    float hz = tanh_fast(p1.z + E.tlo.z + E.ra.z);
    float hw = tanh_fast(p1.w + E.tlo.w + E.ra.w);
    float part = hx * av.x + hy * av.y + hz * av.z + hw * av.w;
    part += __shfl_xor_sync(0xffffffffu, part, 1);
    part += __shfl_xor_sync(0xffffffffu, part, 2);
    float nm = fmaxf(m, part);
    float f = __expf(m - nm);
    float w = __expf(part - nm);
    s = s * f + w;
    acc.x = acc.x * f + w * (E.thi.x + E.gr.x);
    acc.y = acc.y * f + w * (E.thi.y + E.gr.y);
    acc.z = acc.z * f + w * (E.thi.z + E.gr.z);
    acc.w = acc.w * f + w * (E.thi.w + E.gr.w);
    m = nm;
}

__global__ __launch_bounds__(256) void k_main(const float* __restrict__ av_g,
                                              float* __restrict__ out) {
    int tid = threadIdx.x, lane = tid & 31, warp = tid >> 5;
    float4 av = ((const float4*)av_g)[lane];
    const float4* RG = (const float4*)g_RG;

    int gw = blockIdx.x * 8 + warp;
    int nw = gridDim.x * 8;
    for (int ent = gw; ent < NE; ent += nw) {
        int beg = g_rowptr[ent], end = g_rowptr[ent + 1];
        float4 p1 = *(const float4*)(g_P1 + (long)ent * 128 + lane * 4);
        float4 sA = make_float4(0.f, 0.f, 0.f, 0.f);
        float4 sG = sA, acc = sA;
        float m = -1e30f, s = 0.f;

        int deg = end - beg;
        int end2 = beg + (deg & ~1);  // paired portion

        Edge E0, E1;
        if (beg < end2) { fetch_edge(beg, lane, RG, E0); fetch_edge(beg + 1, lane, RG, E1); }
        for (int i = beg; i < end2; i += 2) {
            Edge C0 = E0, C1 = E1;
            if (i + 3 < end2 + 1) {
                fetch_edge(i + 2, lane, RG, E0);
                fetch_edge(i + 3, lane, RG, E1);
            }
            consume(C0, p1, av, sA, sG, acc, m, s);
            consume(C1, p1, av, sA, sG, acc, m, s);
        }
        if (end2 < end) {  // odd tail edge
            Edge Et;
            fetch_edge(end2, lane, RG, Et);
            consume(Et, p1, av, sA, sG, acc, m, s);
        }

        // self-loop edge: rel term = (sum Ra[rel]) / freq
        {
            float inv = (deg > 0) ? 1.f / (float)deg : 1.f;
            Edge Es;
            uint4 t = __ldg((const uint4*)(g_Th + (long)ent * 256 + lane * 8));
            unpack_T(t, Es.tlo, Es.thi);
            Es.ra = make_float4(sA.x * inv, sA.y * inv, sA.z * inv, sA.w * inv);
            Es.gr = make_float4(sG.x * inv, sG.y * inv, sG.z * inv, sG.w * inv);
            float4 dummyA = make_float4(0, 0, 0, 0), dummyG = dummyA;
            consume(Es, p1, av, dummyA, dummyG, acc, m, s);
        }
        float invs = 1.f / (s + 1e-16f);
        float4 o = make_float4(acc.x * invs, acc.y * invs, acc.z * invs, acc.w * invs);
        *(float4*)(out + (long)ent * 128 + lane * 4) = o;
    }
}

extern "C" void kernel_launch(void* const* d_in, const int* in_sizes, int n_in,
                              void* d_out, int out_size) {
    const float* emb_ent = (const float*)d_in[0];
    const float* emb_rel = (const float*)d_in[1];
    const int*   trip    = (const int*)d_in[2];
    const float* Wa      = (const float*)d_in[3];
    const float* ba      = (const float*)d_in[4];
    const float* av      = (const float*)d_in[5];
    const float* Wg      = (const float*)d_in[6];
    const float* bg      = (const float*)d_in[7];
    float* out = (float*)d_out;

    static cudaStream_t s2 = nullptr;
    static cudaEvent_t evFork = nullptr, evJoin = nullptr;
    if (!s2) {
        cudaStreamCreateWithFlags(&s2, cudaStreamNonBlocking);
        cudaEventCreateWithFlags(&evFork, cudaEventDisableTiming);
        cudaEventCreateWithFlags(&evJoin, cudaEventDisableTiming);
        cudaFuncSetAttribute(k_mmagemm, cudaFuncAttributeMaxDynamicSharedMemorySize, SM_TOTAL);
    }

    // fork: CSR chain + relgemm on s2, GEMM chain on s0, join before k_main.
    cudaEventRecord(evFork, 0);
    cudaStreamWaitEvent(s2, evFork, 0);

    k_relgemm<<<NR, 128, 0, s2>>>(emb_rel, Wa, Wg);                 // 1 (s2)
    k_zero<<<(NE + 1 + 255) / 256, 256, 0, s2>>>();                 // 2 (s2)
    k_prepB<<<(3 * 16384 + 255) / 256, 256>>>(Wa, Wg);              // 3 (s0)
    k_mmagemm<<<(NE + 63) / 64, 256, SM_TOTAL>>>(emb_ent, ba, bg);  // 4 (s0)
    k_count<<<(NT + 255) / 256, 256, 0, s2>>>(trip);                // 5 (s2)
    k_scanA<<<NSCB, SCB, 0, s2>>>();                                // 6 (s2)
    k_scanB<<<1, 128, 0, s2>>>();                                   // 7 (s2)
    k_scanC<<<NSCB, SCB, 0, s2>>>();                                // 8 (s2)
    k_scatter<<<(NT + 255) / 256, 256, 0, s2>>>(trip);              // 9 (s2)
    cudaEventRecord(evJoin, s2);

    cudaStreamWaitEvent(0, evJoin, 0);
    k_main<<<1184, 256>>>(av, out);                                 // 10
}

// round 16
// speedup vs baseline: 1.0884x; 1.0122x over previous
#include <cuda_runtime.h>
#include <cuda_bf16.h>
#include <cuda_fp16.h>
#include <math.h>
#include <cstdint>

#define NE 50000
#define NR 64
#define NT 400000

typedef unsigned long long u64;

// Scratch (static __device__ — no runtime allocation)
// g_Th: fp16 head table, lane-interleaved: [ent][lane][0:4]=att ch 4*lane.., [4:8]=msg ch 4*lane..
__device__ __align__(16) __half g_Th[NE * 256];
__device__ float    g_P1[NE * 128];   // emb@Wa1 + ba (tail/att), fp32
__device__ float    g_RG[NR * 256];   // [rel][0:128]=emb_rel@Wa3, [128:256]=emb_rel@Wg2
__device__ int      g_rowptr[NE + 1];
__device__ int      g_cursor[NE];
__device__ unsigned g_elist[NT];      // head | (rel<<16)
__device__ int      g_bsum[128];
__device__ int      g_boff[128];
// Pre-transposed fp16 weight images (hi + residual lo): [group][n][k], group 0=Wa1, 1=Wa2, 2=Wg1
__device__ __align__(16) unsigned short g_Bhi[3 * 16384];
__device__ __align__(16) unsigned short g_Blo[3 * 16384];

// ==================== warp-MMA helpers (sm_80+ PTX, works on sm_103) ====================
__device__ __forceinline__ uint32_t smem_u32(const void* p) {
    uint32_t a;
    asm("{ .reg .u64 t; cvta.to.shared.u64 t, %1; cvt.u32.u64 %0, t; }" : "=r"(a) : "l"(p));
    return a;
}
__device__ __forceinline__ void ldx4(uint32_t r[4], uint32_t addr) {
    asm volatile("ldmatrix.sync.aligned.m8n8.x4.shared.b16 {%0,%1,%2,%3}, [%4];"
                 : "=r"(r[0]), "=r"(r[1]), "=r"(r[2]), "=r"(r[3]) : "r"(addr));
}
__device__ __forceinline__ void mma_f16(float d[4], const uint32_t a[4], const uint32_t* b) {
    asm volatile("mma.sync.aligned.m16n8k16.row.col.f32.f16.f16.f32 "
                 "{%0,%1,%2,%3}, {%4,%5,%6,%7}, {%8,%9}, {%0,%1,%2,%3};"
                 : "+f"(d[0]), "+f"(d[1]), "+f"(d[2]), "+f"(d[3])
                 : "r"(a[0]), "r"(a[1]), "r"(a[2]), "r"(a[3]), "r"(b[0]), "r"(b[1]));
}
__device__ __forceinline__ float tanh_fast(float x) {
    float y; asm("tanh.approx.f32 %0, %1;" : "=f"(y) : "f"(x)); return y;
}

// ---------------- CSR build ----------------
__global__ void k_zero() {
    int i = blockIdx.x * blockDim.x + threadIdx.x;
    if (i <= NE) g_rowptr[i] = 0;
}

__global__ void k_count(const int* __restrict__ trip) {
    int e = blockIdx.x * blockDim.x + threadIdx.x;
    if (e < NT) atomicAdd(&g_rowptr[trip[3 * e + 2]], 1);
}

// 3-stage parallel scan
#define SCB 512
#define NSCB ((NE + SCB - 1) / SCB)   // 98

__global__ void k_scanA() {
    __shared__ int wsum[16];
    int b = blockIdx.x, t = threadIdx.x, lane = t & 31, w = t >> 5;
    int idx = b * SCB + t;
    int v = (idx < NE) ? g_rowptr[idx] : 0;
    #pragma unroll
    for (int o = 16; o > 0; o >>= 1) v += __shfl_down_sync(0xffffffffu, v, o);
    if (lane == 0) wsum[w] = v;
    __syncthreads();
    if (t == 0) {
        int s = 0;
        #pragma unroll
        for (int i = 0; i < 16; i++) s += wsum[i];
        g_bsum[b] = s;
    }
}

__global__ void k_scanB() {
    __shared__ int woff[4];
    int t = threadIdx.x, lane = t & 31, w = t >> 5;
    int v = (t < NSCB) ? g_bsum[t] : 0;
    int incl = v;
    #pragma unroll
    for (int o = 1; o < 32; o <<= 1) {
        int u = __shfl_up_sync(0xffffffffu, incl, o);
        if (lane >= o) incl += u;
    }
    if (lane == 31) woff[w] = incl;
    __syncthreads();
    int base = 0;
    for (int i = 0; i < w; i++) base += woff[i];
    if (t < NSCB) g_boff[t] = base + incl - v;
    if (t == 0) g_rowptr[NE] = NT;
}

__global__ void k_scanC() {
    __shared__ int wsum[16];
    int b = blockIdx.x, t = threadIdx.x, lane = t & 31, w = t >> 5;
    int idx = b * SCB + t;
    int v = (idx < NE) ? g_rowptr[idx] : 0;
    int incl = v;
    #pragma unroll
    for (int o = 1; o < 32; o <<= 1) {
        int u = __shfl_up_sync(0xffffffffu, incl, o);
        if (lane >= o) incl += u;
    }
    if (lane == 31) wsum[w] = incl;
    __syncthreads();
    if (w == 0 && lane < 16) {
        int x = wsum[lane];
        #pragma unroll
        for (int o = 1; o < 16; o <<= 1) {
            int u = __shfl_up_sync(0xffffu, x, o);
            if (lane >= o) x += u;
        }
        wsum[lane] = x;
    }
    __syncthreads();
    int excl = g_boff[b] + (w > 0 ? wsum[w - 1] : 0) + (incl - v);
    if (idx < NE) { g_rowptr[idx] = excl; g_cursor[idx] = excl; }
}

__global__ void k_scatter(const int* __restrict__ trip) {
    int e = blockIdx.x * blockDim.x + threadIdx.x;
    if (e < NT) {
        int h = trip[3 * e], r = trip[3 * e + 1], t = trip[3 * e + 2];
        int pos = atomicAdd(&g_cursor[t], 1);
        g_elist[pos] = (unsigned)h | ((unsigned)r << 16);
    }
}

// ---------------- weight prep: fp32 -> fp16 hi + fp16 residual lo, transposed to [n][k] ----------------
__global__ void k_prepB(const float* __restrict__ Wa, const float* __restrict__ Wg) {
    int idx = blockIdx.x * blockDim.x + threadIdx.x;
    if (idx >= 3 * 16384) return;
    int g = idx >> 14, rem = idx & 16383;
    int n = rem >> 7, k = rem & 127;
    float w = (g == 0) ? Wa[k * 128 + n] : (g == 1) ? Wa[(128 + k) * 128 + n] : Wg[k * 128 + n];
    __half hi = __float2half_rn(w);
    __half lo = __float2half_rn(w - __half2float(hi));
    unsigned short hb, lb;
    memcpy(&hb, &hi, 2); memcpy(&lb, &lo, 2);
    g_Bhi[idx] = hb;
    g_Blo[idx] = lb;
}

// ---------------- relation GEMM, MLP-optimized ----------------
__global__ __launch_bounds__(128) void k_relgemm(const float* __restrict__ emb_rel,
                                                 const float* __restrict__ Wa,
                                                 const float* __restrict__ Wg) {
    __shared__ float er[128];
    int r = blockIdx.x;
    int tid = threadIdx.x;  // 128 threads
    er[tid] = emb_rel[r * 128 + tid];
    __syncthreads();
    int half = tid >> 6;          // 0: Wa-att, 1: Wg-msg
    int j0 = (tid & 63) * 2;      // 2 columns per thread
    const float* W = half ? (Wg + 128 * 128) : (Wa + 256 * 128);
    float ax = 0.f, ay = 0.f;
    #pragma unroll 16
    for (int k = 0; k < 128; k++) {
        float e = er[k];
        float2 w = __ldg((const float2*)(W + k * 128 + j0));
        ax += e * w.x;
        ay += e * w.y;
    }
    float2 o = make_float2(ax, ay);
    *(float2*)(g_RG + r * 256 + half * 128 + j0) = o;
}

// ---------------- HMMA entity GEMM: block M64, 6 B-stages of N64, fp16 2-pass ----------------
// A single fp16; B fp16 hi + residual lo. smem 52224B -> 4 blocks/SM (32 warps).
#define SROW 272
#define SM_A    0
#define SM_B_HI 17408
#define SM_B_LO 34816
#define SM_TOTAL 52224

__global__ __launch_bounds__(256, 4) void k_mmagemm(const float* __restrict__ A,
                                                    const float* __restrict__ ba,
                                                    const float* __restrict__ bg) {
    extern __shared__ char smem[];
    uint32_t sb = smem_u32(smem);
    int tid = threadIdx.x, wid = tid >> 5, lane = tid & 31;
    int rowBase = blockIdx.x * 64;
    int warpM = wid & 1, warpN = wid >> 1;  // 2x4: warp tile 32 rows x 16 cols

    // ---- fill A once (fp32 -> fp16): 64 rows x 128 k ----
    for (int i = tid; i < 2048; i += 256) {
        int m = i >> 5, k4 = (i & 31) * 4;
        int gr = rowBase + m;
        float4 v = make_float4(0.f, 0.f, 0.f, 0.f);
        if (gr < NE) v = *(const float4*)(A + (long)gr * 128 + k4);
        __half2 h01 = __floats2half2_rn(v.x, v.y);
        __half2 h23 = __floats2half2_rn(v.z, v.w);
        int off = m * SROW + k4 * 2;
        *(__half2*)(smem + SM_A + off) = h01;
        *(__half2*)(smem + SM_A + off + 4) = h23;
    }

    uint32_t aAddr = sb + SM_A + (uint32_t)((warpM * 32 + (lane & 15)) * SROW + ((lane >> 4) * 8) * 2);
    uint32_t bAddr = sb + SM_B_HI + (uint32_t)((warpN * 16 + (lane & 7) + ((lane >> 4) << 3)) * SROW
                                               + ((lane >> 3) & 1) * 16);

    int lrow = lane >> 2, lcol = (lane & 3) * 2;

    for (int stage = 0; stage < 6; stage++) {
        int g = stage >> 1, nhalf = stage & 1;
        // ---- fill B stage: 64 rows (n) x 128 k, hi/lo ----
        {
            const uint4* sh = (const uint4*)(g_Bhi + g * 16384 + nhalf * 8192);
            const uint4* sl = (const uint4*)(g_Blo + g * 16384 + nhalf * 8192);
            for (int i = tid; i < 1024; i += 256) {
                int row = i >> 4, c = i & 15;
                int off = row * SROW + c * 16;
                *(uint4*)(smem + SM_B_HI + off) = sh[i];
                *(uint4*)(smem + SM_B_LO + off) = sl[i];
            }
        }
        __syncthreads();

        float acc[2][2][4];
        #pragma unroll
        for (int mt = 0; mt < 2; mt++)
            #pragma unroll
            for (int nt = 0; nt < 2; nt++)
                #pragma unroll
                for (int j = 0; j < 4; j++) acc[mt][nt][j] = 0.f;

        #pragma unroll
        for (int k = 0; k < 8; k++) {
            uint32_t ah[2][4];
            #pragma unroll
            for (int mt = 0; mt < 2; mt++)
                ldx4(ah[mt], aAddr + mt * (16 * SROW) + k * 32);
            uint32_t bh[4], bl[4];
            ldx4(bh, bAddr + k * 32);
            ldx4(bl, bAddr + k * 32 + (SM_B_LO - SM_B_HI));
            #pragma unroll
            for (int nt = 0; nt < 2; nt++) {
                #pragma unroll
                for (int mt = 0; mt < 2; mt++) {
                    mma_f16(acc[mt][nt], ah[mt], bh + 2 * nt);
                    mma_f16(acc[mt][nt], ah[mt], bl + 2 * nt);
                }
            }
        }
        __syncthreads();  // done reading B before next stage overwrite

        // ---- epilogue for this stage ----
        const float* bias = (g == 0) ? ba : (g == 2) ? bg : nullptr;

        #pragma unroll
        for (int mt = 0; mt < 2; mt++) {
            int r0 = rowBase + warpM * 32 + mt * 16 + lrow;
            int r1 = r0 + 8;
            #pragma unroll
            for (int nt = 0; nt < 2; nt++) {
                int n = nhalf * 64 + warpN * 16 + nt * 8 + lcol;  // 0..127, even
                float b0 = 0.f, b1 = 0.f;
                if (bias) { b0 = __ldg(bias + n); b1 = __ldg(bias + n + 1); }
                float v00 = acc[mt][nt][0] + b0, v01 = acc[mt][nt][1] + b1;
                float v10 = acc[mt][nt][2] + b0, v11 = acc[mt][nt][3] + b1;
                if (g == 0) {
                    if (r0 < NE) *(float2*)(g_P1 + (long)r0 * 128 + n) = make_float2(v00, v01);
                    if (r1 < NE) *(float2*)(g_P1 + (long)r1 * 128 + n) = make_float2(v10, v11);
                } else {
                    // lane-interleaved fp16: idx = ent*256 + (n>>2)*8 + (g==2?4:0) + (n&3)
                    int hoff = (n >> 2) * 8 + ((g == 2) ? 4 : 0) + (n & 3);
                    if (r0 < NE) *(__half2*)(g_Th + (long)r0 * 256 + hoff) = __floats2half2_rn(v00, v01);
                    if (r1 < NE) *(__half2*)(g_Th + (long)r1 * 256 + hoff) = __floats2half2_rn(v10, v11);
                }
            }
        }
    }
}

// ---------------- fused edge kernel: pair pipeline + 4-ahead index prefetch ----------------
struct Edge { float4 tlo, thi, ra, gr; };

__device__ __forceinline__ void unpack_T(uint4 t, float4& tlo, float4& thi) {
    float2 a0 = __half22float2(*(__half2*)&t.x);
    float2 a1 = __half22float2(*(__half2*)&t.y);
    float2 m0 = __half22float2(*(__half2*)&t.z);
    float2 m1 = __half22float2(*(__half2*)&t.w);
    tlo = make_float4(a0.x, a0.y, a1.x, a1.y);
    thi = make_float4(m0.x, m0.y, m1.x, m1.y);
}

// gather edge data from a pre-loaded packed index (no elist dependency here)
__device__ __forceinline__ void fetch_data(unsigned pk, int lane, const float4* RG, Edge& E) {
    int h = pk & 0xFFFFu, r = pk >> 16;
    uint4 t = __ldg((const uint4*)(g_Th + (long)h * 256 + lane * 8));
    unpack_T(t, E.tlo, E.thi);
    E.ra  = __ldg(&RG[r * 64 + lane]);
    E.gr  = __ldg(&RG[r * 64 + 32 + lane]);
}

__device__ __forceinline__ void consume(const Edge& E, const float4& p1, const float4& av,
                                        float4& sA, float4& sG, float4& acc, float& m, float& s) {
    sA.x += E.ra.x; sA.y += E.ra.y; sA.z += E.ra.z; sA.w += E.ra.w;
    sG.x += E.gr.x; sG.y += E.gr.y; sG.z += E.gr.z; sG.w += E.gr.w;
    float hx = tanh_fast(p1.x + E.tlo.x + E.ra.x);
    float hy = tanh_fast(p1.y + E.tlo.y + E.ra.y);
    float hz = tanh_fast(p1.z + E.tlo.z + E.ra.z);
    float hw = tanh_fast(p1.w + E.tlo.w + E.ra.w);
    float part = hx * av.x + hy * av.y + hz * av.z + hw * av.w;
    part += __shfl_xor_sync(0xffffffffu, part, 1);
    part += __shfl_xor_sync(0xffffffffu, part, 2);
    float nm = fmaxf(m, part);
    float f = __expf(m - nm);
    float w = __expf(part - nm);
    s = s * f + w;
    acc.x = acc.x * f + w * (E.thi.x + E.gr.x);
    acc.y = acc.y * f + w * (E.thi.y + E.gr.y);
    acc.z = acc.z * f + w * (E.thi.z + E.gr.z);
    acc.w = acc.w * f + w * (E.thi.w + E.gr.w);
    m = nm;
}

__global__ __launch_bounds__(256) void k_main(const float* __restrict__ av_g,
                                              float* __restrict__ out) {
    int tid = threadIdx.x, lane = tid & 31, warp = tid >> 5;
    float4 av = ((const float4*)av_g)[lane];
    const float4* RG = (const float4*)g_RG;

    int gw = blockIdx.x * 8 + warp;
    int nw = gridDim.x * 8;
    for (int ent = gw; ent < NE; ent += nw) {
        int beg = g_rowptr[ent], end = g_rowptr[ent + 1];
        float4 p1 = *(const float4*)(g_P1 + (long)ent * 128 + lane * 4);
        float4 sA = make_float4(0.f, 0.f, 0.f, 0.f);
        float4 sG = sA, acc = sA;
        float m = -1e30f, s = 0.f;

        int deg = end - beg;
        int end2 = beg + (deg & ~1);  // paired portion

        // pipeline: Edge data 2 ahead, packed indices 4 ahead
        Edge E0, E1;
        unsigned pk0 = 0, pk1 = 0;
        if (beg < end2) {
            fetch_data(__ldg(&g_elist[beg]), lane, RG, E0);
            fetch_data(__ldg(&g_elist[beg + 1]), lane, RG, E1);
            if (beg + 2 < end2) {
                pk0 = __ldg(&g_elist[beg + 2]);
                pk1 = __ldg(&g_elist[beg + 3]);
            }
        }
        for (int i = beg; i < end2; i += 2) {
            Edge C0 = E0, C1 = E1;
            if (i + 2 < end2) {
                fetch_data(pk0, lane, RG, E0);
                fetch_data(pk1, lane, RG, E1);
            }
            if (i + 4 < end2) {
                pk0 = __ldg(&g_elist[i + 4]);
                pk1 = __ldg(&g_elist[i + 5]);
            }
            consume(C0, p1, av, sA, sG, acc, m, s);
            consume(C1, p1, av, sA, sG, acc, m, s);
        }
        if (end2 < end) {  // odd tail edge
            Edge Et;
            fetch_data(__ldg(&g_elist[end2]), lane, RG, Et);
            consume(Et, p1, av, sA, sG, acc, m, s);
        }

        // self-loop edge: rel term = (sum Ra[rel]) / freq
        {
            float inv = (deg > 0) ? 1.f / (float)deg : 1.f;
            Edge Es;
            uint4 t = __ldg((const uint4*)(g_Th + (long)ent * 256 + lane * 8));
            unpack_T(t, Es.tlo, Es.thi);
            Es.ra = make_float4(sA.x * inv, sA.y * inv, sA.z * inv, sA.w * inv);
            Es.gr = make_float4(sG.x * inv, sG.y * inv, sG.z * inv, sG.w * inv);
            float4 dummyA = make_float4(0, 0, 0, 0), dummyG = dummyA;
            consume(Es, p1, av, dummyA, dummyG, acc, m, s);
        }
        float invs = 1.f / (s + 1e-16f);
        float4 o = make_float4(acc.x * invs, acc.y * invs, acc.z * invs, acc.w * invs);
        *(float4*)(out + (long)ent * 128 + lane * 4) = o;
    }
}

extern "C" void kernel_launch(void* const* d_in, const int* in_sizes, int n_in,
                              void* d_out, int out_size) {
    const float* emb_ent = (const float*)d_in[0];
    const float* emb_rel = (const float*)d_in[1];
    const int*   trip    = (const int*)d_in[2];
    const float* Wa      = (const float*)d_in[3];
    const float* ba      = (const float*)d_in[4];
    const float* av      = (const float*)d_in[5];
    const float* Wg      = (const float*)d_in[6];
    const float* bg      = (const float*)d_in[7];
    float* out = (float*)d_out;

    static cudaStream_t s2 = nullptr;
    static cudaEvent_t evFork = nullptr, evJoin = nullptr;
    if (!s2) {
        cudaStreamCreateWithFlags(&s2, cudaStreamNonBlocking);
        cudaEventCreateWithFlags(&evFork, cudaEventDisableTiming);
        cudaEventCreateWithFlags(&evJoin, cudaEventDisableTiming);
        cudaFuncSetAttribute(k_mmagemm, cudaFuncAttributeMaxDynamicSharedMemorySize, SM_TOTAL);
    }

    // fork: CSR chain + relgemm on s2, GEMM chain on s0, join before k_main.
    cudaEventRecord(evFork, 0);
    cudaStreamWaitEvent(s2, evFork, 0);

    k_relgemm<<<NR, 128, 0, s2>>>(emb_rel, Wa, Wg);                 // 1 (s2)
    k_zero<<<(NE + 1 + 255) / 256, 256, 0, s2>>>();                 // 2 (s2)
    k_prepB<<<(3 * 16384 + 255) / 256, 256>>>(Wa, Wg);              // 3 (s0)
    k_mmagemm<<<(NE + 63) / 64, 256, SM_TOTAL>>>(emb_ent, ba, bg);  // 4 (s0)
    k_count<<<(NT + 255) / 256, 256, 0, s2>>>(trip);                // 5 (s2)
    k_scanA<<<NSCB, SCB, 0, s2>>>();                                // 6 (s2)
    k_scanB<<<1, 128, 0, s2>>>();                                   // 7 (s2)
    k_scanC<<<NSCB, SCB, 0, s2>>>();                                // 8 (s2)
    k_scatter<<<(NT + 255) / 256, 256, 0, s2>>>(trip);              // 9 (s2)
    cudaEventRecord(evJoin, s2);

    cudaStreamWaitEvent(0, evJoin, 0);
    k_main<<<1184, 256>>>(av, out);                                 // 10
}

// round 17
// speedup vs baseline: 1.1837x; 1.0875x over previous
#include <cuda_runtime.h>
#include <cuda_bf16.h>
#include <cuda_fp16.h>
#include <math.h>
#include <cstdint>

#define NE 50000
#define NR 64
#define NT 400000

typedef unsigned long long u64;

// Scratch (static __device__ — no runtime allocation)
// g_Th: fp16 head table, lane-interleaved: [ent][lane][0:4]=att ch 4*lane.., [4:8]=msg ch 4*lane..
__device__ __align__(16) __half g_Th[NE * 256];
__device__ float    g_P1[NE * 128];   // emb@Wa1 + ba (tail/att), fp32
__device__ float    g_RG[NR * 256];   // [rel][0:128]=emb_rel@Wa3, [128:256]=emb_rel@Wg2
__device__ int      g_rowptr[NE + 1];
__device__ int      g_cursor[NE];
__device__ unsigned g_elist[NT];      // head | (rel<<16)
__device__ int      g_bsum[128];
__device__ int      g_boff[128];
// Pre-transposed fp16 weight image: [group][n][k], group 0=Wa1, 1=Wa2, 2=Wg1
__device__ __align__(16) unsigned short g_Bh[3 * 16384];

// ==================== warp-MMA helpers (sm_80+ PTX, works on sm_103) ====================
__device__ __forceinline__ uint32_t smem_u32(const void* p) {
    uint32_t a;
    asm("{ .reg .u64 t; cvta.to.shared.u64 t, %1; cvt.u32.u64 %0, t; }" : "=r"(a) : "l"(p));
    return a;
}
__device__ __forceinline__ void ldx4(uint32_t r[4], uint32_t addr) {
    asm volatile("ldmatrix.sync.aligned.m8n8.x4.shared.b16 {%0,%1,%2,%3}, [%4];"
                 : "=r"(r[0]), "=r"(r[1]), "=r"(r[2]), "=r"(r[3]) : "r"(addr));
}
__device__ __forceinline__ void mma_f16(float d[4], const uint32_t a[4], const uint32_t* b) {
    asm volatile("mma.sync.aligned.m16n8k16.row.col.f32.f16.f16.f32 "
                 "{%0,%1,%2,%3}, {%4,%5,%6,%7}, {%8,%9}, {%0,%1,%2,%3};"
                 : "+f"(d[0]), "+f"(d[1]), "+f"(d[2]), "+f"(d[3])
                 : "r"(a[0]), "r"(a[1]), "r"(a[2]), "r"(a[3]), "r"(b[0]), "r"(b[1]));
}
__device__ __forceinline__ float tanh_fast(float x) {
    float y; asm("tanh.approx.f32 %0, %1;" : "=f"(y) : "f"(x)); return y;
}

// ---------------- CSR build ----------------
__global__ void k_zero() {
    int i = blockIdx.x * blockDim.x + threadIdx.x;
    if (i <= NE) g_rowptr[i] = 0;
}

__global__ void k_count(const int* __restrict__ trip) {
    int e = blockIdx.x * blockDim.x + threadIdx.x;
    if (e < NT) atomicAdd(&g_rowptr[trip[3 * e + 2]], 1);
}

// 3-stage parallel scan
#define SCB 512
#define NSCB ((NE + SCB - 1) / SCB)   // 98

__global__ void k_scanA() {
    __shared__ int wsum[16];
    int b = blockIdx.x, t = threadIdx.x, lane = t & 31, w = t >> 5;
    int idx = b * SCB + t;
    int v = (idx < NE) ? g_rowptr[idx] : 0;
    #pragma unroll
    for (int o = 16; o > 0; o >>= 1) v += __shfl_down_sync(0xffffffffu, v, o);
    if (lane == 0) wsum[w] = v;
    __syncthreads();
    if (t == 0) {
        int s = 0;
        #pragma unroll
        for (int i = 0; i < 16; i++) s += wsum[i];
        g_bsum[b] = s;
    }
}

__global__ void k_scanB() {
    __shared__ int woff[4];
    int t = threadIdx.x, lane = t & 31, w = t >> 5;
    int v = (t < NSCB) ? g_bsum[t] : 0;
    int incl = v;
    #pragma unroll
    for (int o = 1; o < 32; o <<= 1) {
        int u = __shfl_up_sync(0xffffffffu, incl, o);
        if (lane >= o) incl += u;
    }
    if (lane == 31) woff[w] = incl;
    __syncthreads();
    int base = 0;
    for (int i = 0; i < w; i++) base += woff[i];
    if (t < NSCB) g_boff[t] = base + incl - v;
    if (t == 0) g_rowptr[NE] = NT;
}

__global__ void k_scanC() {
    __shared__ int wsum[16];
    int b = blockIdx.x, t = threadIdx.x, lane = t & 31, w = t >> 5;
    int idx = b * SCB + t;
    int v = (idx < NE) ? g_rowptr[idx] : 0;
    int incl = v;
    #pragma unroll
    for (int o = 1; o < 32; o <<= 1) {
        int u = __shfl_up_sync(0xffffffffu, incl, o);
        if (lane >= o) incl += u;
    }
    if (lane == 31) wsum[w] = incl;
    __syncthreads();
    if (w == 0 && lane < 16) {
        int x = wsum[lane];
        #pragma unroll
        for (int o = 1; o < 16; o <<= 1) {
            int u = __shfl_up_sync(0xffffu, x, o);
            if (lane >= o) x += u;
        }
        wsum[lane] = x;
    }
    __syncthreads();
    int excl = g_boff[b] + (w > 0 ? wsum[w - 1] : 0) + (incl - v);
    if (idx < NE) { g_rowptr[idx] = excl; g_cursor[idx] = excl; }
}

__global__ void k_scatter(const int* __restrict__ trip) {
    int e = blockIdx.x * blockDim.x + threadIdx.x;
    if (e < NT) {
        int h = trip[3 * e], r = trip[3 * e + 1], t = trip[3 * e + 2];
        int pos = atomicAdd(&g_cursor[t], 1);
        g_elist[pos] = (unsigned)h | ((unsigned)r << 16);
    }
}

// ---------------- weight prep: fp32 -> fp16, transposed to [n][k] ----------------
__global__ void k_prepB(const float* __restrict__ Wa, const float* __restrict__ Wg) {
    int idx = blockIdx.x * blockDim.x + threadIdx.x;
    if (idx >= 3 * 16384) return;
    int g = idx >> 14, rem = idx & 16383;
    int n = rem >> 7, k = rem & 127;
    float w = (g == 0) ? Wa[k * 128 + n] : (g == 1) ? Wa[(128 + k) * 128 + n] : Wg[k * 128 + n];
    __half hi = __float2half_rn(w);
    unsigned short hb;
    memcpy(&hb, &hi, 2);
    g_Bh[idx] = hb;
}

// ---------------- relation GEMM, MLP-optimized ----------------
__global__ __launch_bounds__(128) void k_relgemm(const float* __restrict__ emb_rel,
                                                 const float* __restrict__ Wa,
                                                 const float* __restrict__ Wg) {
    __shared__ float er[128];
    int r = blockIdx.x;
    int tid = threadIdx.x;  // 128 threads
    er[tid] = emb_rel[r * 128 + tid];
    __syncthreads();
    int half = tid >> 6;          // 0: Wa-att, 1: Wg-msg
    int j0 = (tid & 63) * 2;      // 2 columns per thread
    const float* W = half ? (Wg + 128 * 128) : (Wa + 256 * 128);
    float ax = 0.f, ay = 0.f;
    #pragma unroll 16
    for (int k = 0; k < 128; k++) {
        float e = er[k];
        float2 w = __ldg((const float2*)(W + k * 128 + j0));
        ax += e * w.x;
        ay += e * w.y;
    }
    float2 o = make_float2(ax, ay);
    *(float2*)(g_RG + r * 256 + half * 128 + j0) = o;
}

// ---------------- HMMA entity GEMM: block M64, 6 B-stages of N64, single-pass fp16 ----------------
// smem 34816B. Regs cap occupancy at ~4 blocks/SM (32 warps).
#define SROW 272
#define SM_A   0
#define SM_B   17408
#define SM_TOTAL 34816

__global__ __launch_bounds__(256, 4) void k_mmagemm(const float* __restrict__ A,
                                                    const float* __restrict__ ba,
                                                    const float* __restrict__ bg) {
    extern __shared__ char smem[];
    uint32_t sb = smem_u32(smem);
    int tid = threadIdx.x, wid = tid >> 5, lane = tid & 31;
    int rowBase = blockIdx.x * 64;
    int warpM = wid & 1, warpN = wid >> 1;  // 2x4: warp tile 32 rows x 16 cols

    // ---- fill A once (fp32 -> fp16): 64 rows x 128 k ----
    for (int i = tid; i < 2048; i += 256) {
        int m = i >> 5, k4 = (i & 31) * 4;
        int gr = rowBase + m;
        float4 v = make_float4(0.f, 0.f, 0.f, 0.f);
        if (gr < NE) v = *(const float4*)(A + (long)gr * 128 + k4);
        __half2 h01 = __floats2half2_rn(v.x, v.y);
        __half2 h23 = __floats2half2_rn(v.z, v.w);
        int off = m * SROW + k4 * 2;
        *(__half2*)(smem + SM_A + off) = h01;
        *(__half2*)(smem + SM_A + off + 4) = h23;
    }

    uint32_t aAddr = sb + SM_A + (uint32_t)((warpM * 32 + (lane & 15)) * SROW + ((lane >> 4) * 8) * 2);
    uint32_t bAddr = sb + SM_B + (uint32_t)((warpN * 16 + (lane & 7) + ((lane >> 4) << 3)) * SROW
                                            + ((lane >> 3) & 1) * 16);

    int lrow = lane >> 2, lcol = (lane & 3) * 2;

    for (int stage = 0; stage < 6; stage++) {
        int g = stage >> 1, nhalf = stage & 1;
        // ---- fill B stage: 64 rows (n) x 128 k ----
        {
            const uint4* sh = (const uint4*)(g_Bh + g * 16384 + nhalf * 8192);
            for (int i = tid; i < 1024; i += 256) {
                int row = i >> 4, c = i & 15;
                int off = row * SROW + c * 16;
                *(uint4*)(smem + SM_B + off) = sh[i];
            }
        }
        __syncthreads();

        float acc[2][2][4];
        #pragma unroll
        for (int mt = 0; mt < 2; mt++)
            #pragma unroll
            for (int nt = 0; nt < 2; nt++)
                #pragma unroll
                for (int j = 0; j < 4; j++) acc[mt][nt][j] = 0.f;

        #pragma unroll
        for (int k = 0; k < 8; k++) {
            uint32_t ah[2][4];
            #pragma unroll
            for (int mt = 0; mt < 2; mt++)
                ldx4(ah[mt], aAddr + mt * (16 * SROW) + k * 32);
            uint32_t bh[4];
            ldx4(bh, bAddr + k * 32);
            #pragma unroll
            for (int nt = 0; nt < 2; nt++)
                #pragma unroll
                for (int mt = 0; mt < 2; mt++)
                    mma_f16(acc[mt][nt], ah[mt], bh + 2 * nt);
        }
        __syncthreads();  // done reading B before next stage overwrite

        // ---- epilogue for this stage ----
        const float* bias = (g == 0) ? ba : (g == 2) ? bg : nullptr;

        #pragma unroll
        for (int mt = 0; mt < 2; mt++) {
            int r0 = rowBase + warpM * 32 + mt * 16 + lrow;
            int r1 = r0 + 8;
            #pragma unroll
            for (int nt = 0; nt < 2; nt++) {
                int n = nhalf * 64 + warpN * 16 + nt * 8 + lcol;  // 0..127, even
                float b0 = 0.f, b1 = 0.f;
                if (bias) { b0 = __ldg(bias + n); b1 = __ldg(bias + n + 1); }
                float v00 = acc[mt][nt][0] + b0, v01 = acc[mt][nt][1] + b1;
                float v10 = acc[mt][nt][2] + b0, v11 = acc[mt][nt][3] + b1;
                if (g == 0) {
                    if (r0 < NE) *(float2*)(g_P1 + (long)r0 * 128 + n) = make_float2(v00, v01);
                    if (r1 < NE) *(float2*)(g_P1 + (long)r1 * 128 + n) = make_float2(v10, v11);
                } else {
                    // lane-interleaved fp16: idx = ent*256 + (n>>2)*8 + (g==2?4:0) + (n&3)
                    int hoff = (n >> 2) * 8 + ((g == 2) ? 4 : 0) + (n & 3);
                    if (r0 < NE) *(__half2*)(g_Th + (long)r0 * 256 + hoff) = __floats2half2_rn(v00, v01);
                    if (r1 < NE) *(__half2*)(g_Th + (long)r1 * 256 + hoff) = __floats2half2_rn(v10, v11);
                }
            }
        }
    }
}

// ---------------- fused edge kernel: pair-pipelined online softmax, fp16 T gathers ----------------
struct Edge { float4 tlo, thi, ra, gr; };

__device__ __forceinline__ void unpack_T(uint4 t, float4& tlo, float4& thi) {
    float2 a0 = __half22float2(*(__half2*)&t.x);
    float2 a1 = __half22float2(*(__half2*)&t.y);
    float2 m0 = __half22float2(*(__half2*)&t.z);
    float2 m1 = __half22float2(*(__half2*)&t.w);
    tlo = make_float4(a0.x, a0.y, a1.x, a1.y);
    thi = make_float4(m0.x, m0.y, m1.x, m1.y);
}

__device__ __forceinline__ void fetch_edge(int idx, int lane, const float4* RG, Edge& E) {
    unsigned pk = __ldg(&g_elist[idx]);
    int h = pk & 0xFFFFu, r = pk >> 16;
    uint4 t = __ldg((const uint4*)(g_Th + (long)h * 256 + lane * 8));
    unpack_T(t, E.tlo, E.thi);
    E.ra  = __ldg(&RG[r * 64 + lane]);
    E.gr  = __ldg(&RG[r * 64 + 32 + lane]);
}

__device__ __forceinline__ void consume(const Edge& E, const float4& p1, const float4& av,
                                        float4& sA, float4& sG, float4& acc, float& m, float& s) {
    sA.x += E.ra.x; sA.y += E.ra.y; sA.z += E.ra.z; sA.w += E.ra.w;
    sG.x += E.gr.x; sG.y += E.gr.y; sG.z += E.gr.z; sG.w += E.gr.w;
    float hx = tanh_fast(p1.x + E.tlo.x + E.ra.x);
    float hy = tanh_fast(p1.y + E.tlo.y + E.ra.y);
    float hz = tanh_fast(p1.z + E.tlo.z + E.ra.z);
    float hw = tanh_fast(p1.w + E.tlo.w + E.ra.w);
    float part = hx * av.x + hy * av.y + hz * av.z + hw * av.w;
    part += __shfl_xor_sync(0xffffffffu, part, 1);
    part += __shfl_xor_sync(0xffffffffu, part, 2);
    float nm = fmaxf(m, part);
    float f = __expf(m - nm);
    float w = __expf(part - nm);
    s = s * f + w;
    acc.x = acc.x * f + w * (E.thi.x + E.gr.x);
    acc.y = acc.y * f + w * (E.thi.y + E.gr.y);
    acc.z = acc.z * f + w * (E.thi.z + E.gr.z);
    acc.w = acc.w * f + w * (E.thi.w + E.gr.w);
    m = nm;
}

__global__ __launch_bounds__(256) void k_main(const float* __restrict__ av_g,
                                              float* __restrict__ out) {
    int tid = threadIdx.x, lane = tid & 31, warp = tid >> 5;
    float4 av = ((const float4*)av_g)[lane];
    const float4* RG = (const float4*)g_RG;

    int gw = blockIdx.x * 8 + warp;
    int nw = gridDim.x * 8;
    for (int ent = gw; ent < NE; ent += nw) {
        int beg = g_rowptr[ent], end = g_rowptr[ent + 1];
        float4 p1 = *(const float4*)(g_P1 + (long)ent * 128 + lane * 4);
        float4 sA = make_float4(0.f, 0.f, 0.f, 0.f);
        float4 sG = sA, acc = sA;
        float m = -1e30f, s = 0.f;

        int deg = end - beg;
        int end2 = beg + (deg & ~1);  // paired portion

        Edge E0, E1;
        if (beg < end2) { fetch_edge(beg, lane, RG, E0); fetch_edge(beg + 1, lane, RG, E1); }
        for (int i = beg; i < end2; i += 2) {
            Edge C0 = E0, C1 = E1;
            if (i + 2 < end2) {
                fetch_edge(i + 2, lane, RG, E0);
                fetch_edge(i + 3, lane, RG, E1);
            }
            consume(C0, p1, av, sA, sG, acc, m, s);
            consume(C1, p1, av, sA, sG, acc, m, s);
        }
        if (end2 < end) {  // odd tail edge
            Edge Et;
            fetch_edge(end2, lane, RG, Et);
            consume(Et, p1, av, sA, sG, acc, m, s);
        }

        // self-loop edge: rel term = (sum Ra[rel]) / freq
        {
            float inv = (deg > 0) ? 1.f / (float)deg : 1.f;
            Edge Es;
            uint4 t = __ldg((const uint4*)(g_Th + (long)ent * 256 + lane * 8));
            unpack_T(t, Es.tlo, Es.thi);
            Es.ra = make_float4(sA.x * inv, sA.y * inv, sA.z * inv, sA.w * inv);
            Es.gr = make_float4(sG.x * inv, sG.y * inv, sG.z * inv, sG.w * inv);
            float4 dummyA = make_float4(0, 0, 0, 0), dummyG = dummyA;
            consume(Es, p1, av, dummyA, dummyG, acc, m, s);
        }
        float invs = 1.f / (s + 1e-16f);
        float4 o = make_float4(acc.x * invs, acc.y * invs, acc.z * invs, acc.w * invs);
        *(float4*)(out + (long)ent * 128 + lane * 4) = o;
    }
}

extern "C" void kernel_launch(void* const* d_in, const int* in_sizes, int n_in,
                              void* d_out, int out_size) {
    const float* emb_ent = (const float*)d_in[0];
    const float* emb_rel = (const float*)d_in[1];
    const int*   trip    = (const int*)d_in[2];
    const float* Wa      = (const float*)d_in[3];
    const float* ba      = (const float*)d_in[4];
    const float* av      = (const float*)d_in[5];
    const float* Wg      = (const float*)d_in[6];
    const float* bg      = (const float*)d_in[7];
    float* out = (float*)d_out;

    static cudaStream_t s2 = nullptr;
    static cudaEvent_t evFork = nullptr, evJoin = nullptr;
    if (!s2) {
        cudaStreamCreateWithFlags(&s2, cudaStreamNonBlocking);
        cudaEventCreateWithFlags(&evFork, cudaEventDisableTiming);
        cudaEventCreateWithFlags(&evJoin, cudaEventDisableTiming);
        cudaFuncSetAttribute(k_mmagemm, cudaFuncAttributeMaxDynamicSharedMemorySize, SM_TOTAL);
    }

    // fork: CSR chain + relgemm on s2, GEMM chain on s0, join before k_main.
    cudaEventRecord(evFork, 0);
    cudaStreamWaitEvent(s2, evFork, 0);

    k_relgemm<<<NR, 128, 0, s2>>>(emb_rel, Wa, Wg);                 // 1 (s2)
    k_zero<<<(NE + 1 + 255) / 256, 256, 0, s2>>>();                 // 2 (s2)
    k_prepB<<<(3 * 16384 + 255) / 256, 256>>>(Wa, Wg);              // 3 (s0)
    k_mmagemm<<<(NE + 63) / 64, 256, SM_TOTAL>>>(emb_ent, ba, bg);  // 4 (s0)
    k_count<<<(NT + 255) / 256, 256, 0, s2>>>(trip);                // 5 (s2)
    k_scanA<<<NSCB, SCB, 0, s2>>>();                                // 6 (s2)
    k_scanB<<<1, 128, 0, s2>>>();                                   // 7 (s2)
    k_scanC<<<NSCB, SCB, 0, s2>>>();                                // 8 (s2)
    k_scatter<<<(NT + 255) / 256, 256, 0, s2>>>(trip);              // 9 (s2)
    cudaEventRecord(evJoin, s2);

    cudaStreamWaitEvent(0, evJoin, 0);
    k_main<<<1184, 256>>>(av, out);                                 // 10
}